// round 2
// baseline (speedup 1.0000x reference)
#include <cuda_runtime.h>

#define NN 100000
#define RR 3
#define EE 800000
#define LL 200000

// ---------------- scratch (static device globals: no runtime allocation) ----------------
__device__ __align__(16) float g_agg[(size_t)RR * NN * 64];  // segment-sum buffer (76.8MB)
__device__ __align__(16) float g_h[(size_t)RR * NN * 64];    // graphconv output   (76.8MB)
__device__ __align__(16) float g_mix[(size_t)NN * 64];       // attention-mixed features
__device__ __align__(16) float g_z[(size_t)NN * 2];          // final projection
__device__ float g_colsum[RR * 64];
__device__ float g_attn[RR];

// NOTE: macro parameter must NOT be named 'w' — member access .w would be substituted.
#define DOT4(acc, W_, v, k) \
    acc += (W_).x * (v)[4*(k)] + (W_).y * (v)[4*(k)+1] + (W_).z * (v)[4*(k)+2] + (W_).w * (v)[4*(k)+3]

// ---------------- zero agg buffer + colsum ----------------
__global__ void k_zero() {
    int i = blockIdx.x * blockDim.x + threadIdx.x;
    const int tot4 = RR * NN * 16;
    if (i < tot4) ((float4*)g_agg)[i] = make_float4(0.f, 0.f, 0.f, 0.f);
    if (i < RR * 64) g_colsum[i] = 0.f;
}

// ---------------- scatter: agg[r][dst] += feat[src] ----------------
__global__ void k_scatter(const float* __restrict__ feat, int use_mix,
                          const int* __restrict__ ei) {
    unsigned idx = blockIdx.x * blockDim.x + threadIdx.x;
    if (idx >= (unsigned)RR * EE * 16u) return;
    const float* f = use_mix ? g_mix : feat;
    unsigned chunk = idx & 15u;
    unsigned e = idx >> 4;
    unsigned r = e / EE;
    unsigned eo = e - r * EE;
    int s = ei[(size_t)r * 2 * EE + eo];
    int d = ei[(size_t)r * 2 * EE + EE + eo];
    float4 v = *(const float4*)(f + (size_t)s * 64 + chunk * 4);
    float* o = g_agg + ((size_t)r * NN + d) * 64 + chunk * 4;
    atomicAdd(o + 0, v.x);
    atomicAdd(o + 1, v.y);
    atomicAdd(o + 2, v.z);
    atomicAdd(o + 3, v.w);
}

// ---------------- graphconv: g_h = relu(agg @ Wrel.T + b + root @ Wroot.T) ----------------
__global__ __launch_bounds__(128) void k_conv(
    const float* __restrict__ root_in, int use_mix,
    const float* __restrict__ Wrel, const float* __restrict__ brel,
    const float* __restrict__ Wroot) {
    extern __shared__ float sm[];
    float* sWa  = sm;          // 4096
    float* sWb  = sm + 4096;   // 4096
    float* sB   = sm + 8192;   // 64
    float* sOut = sm + 8256;   // 128*65
    const int r = blockIdx.y;
    const int tid = threadIdx.x;
    const int node0 = blockIdx.x * 128;
    const int node = min(node0 + tid, NN - 1);
    const float* rp = use_mix ? g_mix : root_in;
    {
        const float4* wr = (const float4*)(Wrel + (size_t)r * 4096);
        const float4* wo = (const float4*)(Wroot + (size_t)r * 4096);
        for (int i = tid; i < 1024; i += 128) {
            ((float4*)sWa)[i] = wr[i];
            ((float4*)sWb)[i] = wo[i];
        }
        if (tid < 64) sB[tid] = brel[r * 64 + tid];
    }
    __syncthreads();

    float va[64], vb[64];
    const float4* ap = (const float4*)(g_agg + ((size_t)r * NN + node) * 64);
    const float4* bp = (const float4*)(rp + (size_t)node * 64);
#pragma unroll
    for (int i = 0; i < 16; i++) {
        float4 t = ap[i]; va[4*i]=t.x; va[4*i+1]=t.y; va[4*i+2]=t.z; va[4*i+3]=t.w;
        float4 u = bp[i]; vb[4*i]=u.x; vb[4*i+1]=u.y; vb[4*i+2]=u.z; vb[4*i+3]=u.w;
    }
    for (int c = 0; c < 64; c++) {
        const float4* wa = (const float4*)(sWa + c * 64);
        const float4* wb = (const float4*)(sWb + c * 64);
        float a0 = sB[c], a1 = 0.f, a2 = 0.f, a3 = 0.f;
#pragma unroll
        for (int k = 0; k < 16; k++) {
            float4 w1 = wa[k];
            a0 += w1.x * va[4*k];     a1 += w1.y * va[4*k+1];
            a2 += w1.z * va[4*k+2];   a3 += w1.w * va[4*k+3];
            float4 w2 = wb[k];
            a0 += w2.x * vb[4*k];     a1 += w2.y * vb[4*k+1];
            a2 += w2.z * vb[4*k+2];   a3 += w2.w * vb[4*k+3];
        }
        sOut[tid * 65 + c] = fmaxf(a0 + a1 + a2 + a3, 0.f);
    }
    __syncthreads();
    float* dst = g_h + ((size_t)r * NN + node0) * 64;
    int total = min(128, NN - node0) * 64;
    for (int i = tid; i < total; i += 128)
        dst[i] = sOut[(i >> 6) * 65 + (i & 63)];
}

// ---------------- GRU: cur = (1-z)*n + z*past ----------------
__global__ __launch_bounds__(128) void k_gru(
    const float* __restrict__ past,
    const float* __restrict__ Wi, const float* __restrict__ Wh,
    const float* __restrict__ bi, const float* __restrict__ bh,
    float* __restrict__ cur) {
    extern __shared__ float sm[];
    float* sWi  = sm;           // 12288
    float* sBi  = sm + 12288;   // 192
    float* sBh  = sm + 12480;   // 192
    float* sOut = sm + 12672;   // 128*65
    const int r = blockIdx.y;
    const int tid = threadIdx.x;
    const int node0 = blockIdx.x * 128;
    const int node = min(node0 + tid, NN - 1);
    {
        const float4* w = (const float4*)Wi;
        for (int i = tid; i < 3072; i += 128) ((float4*)sWi)[i] = w[i];
        if (tid < 64) {
            sBi[tid] = bi[tid]; sBi[64+tid] = bi[64+tid]; sBi[128+tid] = bi[128+tid];
            sBh[tid] = bh[tid]; sBh[64+tid] = bh[64+tid]; sBh[128+tid] = bh[128+tid];
        }
    }
    __syncthreads();

    float h[64], pv[64];
    const float4* hp = (const float4*)(g_h + ((size_t)r * NN + node) * 64);
    const float* pbase = past + ((size_t)r * NN + node) * 64;
    const float4* pp = (const float4*)pbase;
#pragma unroll
    for (int i = 0; i < 16; i++) {
        float4 t = hp[i]; h[4*i]=t.x;  h[4*i+1]=t.y;  h[4*i+2]=t.z;  h[4*i+3]=t.w;
        float4 u = pp[i]; pv[4*i]=u.x; pv[4*i+1]=u.y; pv[4*i+2]=u.z; pv[4*i+3]=u.w;
    }
    for (int c = 0; c < 64; c++) {
        const float4* wir = (const float4*)(sWi + c * 64);
        const float4* wiz = (const float4*)(sWi + (64 + c) * 64);
        const float4* win = (const float4*)(sWi + (128 + c) * 64);
        const float4* whr = (const float4*)(Wh + (size_t)c * 64);
        const float4* whz = (const float4*)(Wh + (size_t)(64 + c) * 64);
        const float4* whn = (const float4*)(Wh + (size_t)(128 + c) * 64);
        float air = sBi[c], aiz = sBi[64+c], ain = sBi[128+c];
        float ahr = sBh[c], ahz = sBh[64+c], ahn = sBh[128+c];
#pragma unroll
        for (int k = 0; k < 16; k++) {
            float4 w0 = wir[k]; DOT4(air, w0, h, k);
            float4 w1 = wiz[k]; DOT4(aiz, w1, h, k);
            float4 w2 = win[k]; DOT4(ain, w2, h, k);
            float4 w3 = whr[k]; DOT4(ahr, w3, pv, k);
            float4 w4 = whz[k]; DOT4(ahz, w4, pv, k);
            float4 w5 = whn[k]; DOT4(ahn, w5, pv, k);
        }
        float rg = 1.f / (1.f + __expf(-(air + ahr)));
        float zg = 1.f / (1.f + __expf(-(aiz + ahz)));
        float ng = tanhf(ain + rg * ahn);
        float p  = pbase[c];
        sOut[tid * 65 + c] = (1.f - zg) * ng + zg * p;
    }
    __syncthreads();
    float* dst = cur + ((size_t)r * NN + node0) * 64;
    int total = min(128, NN - node0) * 64;
    for (int i = tid; i < total; i += 128)
        dst[i] = sOut[(i >> 6) * 65 + (i & 63)];
}

// ---------------- semantic-attention column sums: colsum[r][c] += tanh(cur@kW.T+kb)[c] ----------------
__global__ __launch_bounds__(128) void k_att(
    const float* __restrict__ cur, const float* __restrict__ kW,
    const float* __restrict__ kb) {
    extern __shared__ float sm[];
    float* sW = sm;          // 4096
    float* sb = sm + 4096;   // 64
    const int r = blockIdx.y;
    const int tid = threadIdx.x;
    const int noden = blockIdx.x * 128 + tid;
    const bool act = noden < NN;
    const int node = act ? noden : NN - 1;
    for (int i = tid; i < 1024; i += 128) ((float4*)sW)[i] = ((const float4*)kW)[i];
    if (tid < 64) sb[tid] = kb[tid];
    __syncthreads();

    float cv[64];
    const float4* cp = (const float4*)(cur + ((size_t)r * NN + node) * 64);
#pragma unroll
    for (int i = 0; i < 16; i++) {
        float4 t = cp[i]; cv[4*i]=t.x; cv[4*i+1]=t.y; cv[4*i+2]=t.z; cv[4*i+3]=t.w;
    }
    int lane = tid & 31;
    for (int c = 0; c < 64; c++) {
        const float4* w = (const float4*)(sW + c * 64);
        float a0 = sb[c], a1 = 0.f, a2 = 0.f, a3 = 0.f;
#pragma unroll
        for (int k = 0; k < 16; k++) {
            float4 ww = w[k];
            a0 += ww.x * cv[4*k];   a1 += ww.y * cv[4*k+1];
            a2 += ww.z * cv[4*k+2]; a3 += ww.w * cv[4*k+3];
        }
        float t = act ? tanhf(a0 + a1 + a2 + a3) : 0.f;
#pragma unroll
        for (int o = 16; o; o >>= 1) t += __shfl_down_sync(0xffffffffu, t, o);
        if (lane == 0) atomicAdd(&g_colsum[r * 64 + c], t);
    }
}

// ---------------- softmax over relations ----------------
__global__ void k_softmax(const float* __restrict__ q) {
    int lane = threadIdx.x;
    float s0 = 0.f, s1 = 0.f, s2 = 0.f;
    for (int c = lane; c < 64; c += 32) {
        float qc = q[c];
        s0 += qc * g_colsum[c];
        s1 += qc * g_colsum[64 + c];
        s2 += qc * g_colsum[128 + c];
    }
#pragma unroll
    for (int o = 16; o; o >>= 1) {
        s0 += __shfl_down_sync(0xffffffffu, s0, o);
        s1 += __shfl_down_sync(0xffffffffu, s1, o);
        s2 += __shfl_down_sync(0xffffffffu, s2, o);
    }
    if (lane == 0) {
        const float inv = 1.0f / (float)NN;
        s0 *= inv; s1 *= inv; s2 *= inv;
        float m = fmaxf(s0, fmaxf(s1, s2));
        float e0 = __expf(s0 - m), e1 = __expf(s1 - m), e2 = __expf(s2 - m);
        float d = 1.f / (e0 + e1 + e2);
        g_attn[0] = e0 * d; g_attn[1] = e1 * d; g_attn[2] = e2 * d;
    }
}

// ---------------- attention mix: g_mix = sum_r attn[r]*cur[r] ----------------
__global__ void k_mix(const float* __restrict__ cur) {
    int i = blockIdx.x * blockDim.x + threadIdx.x;
    if (i >= NN * 16) return;
    float a0 = g_attn[0], a1 = g_attn[1], a2 = g_attn[2];
    const float4* c = (const float4*)cur;
    float4 v0 = c[i], v1 = c[i + (size_t)NN * 16], v2 = c[i + (size_t)2 * NN * 16];
    float4 o;
    o.x = a0*v0.x + a1*v1.x + a2*v2.x;
    o.y = a0*v0.y + a1*v1.y + a2*v2.y;
    o.z = a0*v0.z + a1*v1.z + a2*v2.z;
    o.w = a0*v0.w + a1*v1.w + a2*v2.w;
    ((float4*)g_mix)[i] = o;
}

// ---------------- final projection z = (sum_r attn[r]*cur2[r]) @ postW.T + postb ----------------
__global__ __launch_bounds__(128) void k_zfuse(
    const float* __restrict__ cur2, const float* __restrict__ postW,
    const float* __restrict__ postb) {
    int node = blockIdx.x * blockDim.x + threadIdx.x;
    if (node >= NN) return;
    float a0 = g_attn[0], a1 = g_attn[1], a2 = g_attn[2];
    const float4* c0 = (const float4*)(cur2 + (size_t)node * 64);
    const float4* c1 = (const float4*)(cur2 + ((size_t)NN + node) * 64);
    const float4* c2 = (const float4*)(cur2 + ((size_t)2 * NN + node) * 64);
    const float4* w0 = (const float4*)postW;
    const float4* w1 = (const float4*)(postW + 64);
    float z0 = postb[0], z1 = postb[1];
#pragma unroll
    for (int i = 0; i < 16; i++) {
        float4 u0 = c0[i], u1 = c1[i], u2 = c2[i];
        float4 m;
        m.x = a0*u0.x + a1*u1.x + a2*u2.x;
        m.y = a0*u0.y + a1*u1.y + a2*u2.y;
        m.z = a0*u0.z + a1*u1.z + a2*u2.z;
        m.w = a0*u0.w + a1*u1.w + a2*u2.w;
        float4 p0 = w0[i], p1 = w1[i];
        z0 += m.x*p0.x + m.y*p0.y + m.z*p0.z + m.w*p0.w;
        z1 += m.x*p1.x + m.y*p1.y + m.z*p1.z + m.w*p1.w;
    }
    g_z[2 * node]     = z0;
    g_z[2 * node + 1] = z1;
}

// ---------------- link scores ----------------
__global__ void k_score(const int* __restrict__ eli, const float* __restrict__ rel,
                        float* __restrict__ scores) {
    int idx = blockIdx.x * blockDim.x + threadIdx.x;
    if (idx >= RR * LL) return;
    int r = idx / LL;
    int l = idx - r * LL;
    int hd = eli[(size_t)r * 2 * LL + l];
    int tl = eli[(size_t)r * 2 * LL + LL + l];
    float hr = g_z[2 * hd], hi = g_z[2 * hd + 1];
    float tr = g_z[2 * tl], ti = g_z[2 * tl + 1];
    float rr = rel[2 * r], ri = rel[2 * r + 1];
    scores[idx] = hr * rr * tr + hi * rr * ti + hr * ri * ti - hi * ri * tr;
}

// ---------------- host ----------------
extern "C" void kernel_launch(void* const* d_in, const int* in_sizes, int n_in,
                              void* d_out, int out_size) {
    const float* x      = (const float*)d_in[0];
    const int*   ei     = (const int*)d_in[1];
    const int*   eli    = (const int*)d_in[2];
    const float* past1  = (const float*)d_in[3];
    const float* past2  = (const float*)d_in[4];
    const float* W1rel  = (const float*)d_in[5];
    const float* b1rel  = (const float*)d_in[6];
    const float* W1root = (const float*)d_in[7];
    const float* g1Wi   = (const float*)d_in[8];
    const float* g1Wh   = (const float*)d_in[9];
    const float* g1bi   = (const float*)d_in[10];
    const float* g1bh   = (const float*)d_in[11];
    const float* k1W    = (const float*)d_in[12];
    const float* k1b    = (const float*)d_in[13];
    const float* q1     = (const float*)d_in[14];
    const float* W2rel  = (const float*)d_in[15];
    const float* b2rel  = (const float*)d_in[16];
    const float* W2root = (const float*)d_in[17];
    const float* g2Wi   = (const float*)d_in[18];
    const float* g2Wh   = (const float*)d_in[19];
    const float* g2bi   = (const float*)d_in[20];
    const float* g2bh   = (const float*)d_in[21];
    const float* k2W    = (const float*)d_in[22];
    const float* k2b    = (const float*)d_in[23];
    const float* q2     = (const float*)d_in[24];
    const float* postW  = (const float*)d_in[25];
    const float* postb  = (const float*)d_in[26];
    const float* relemb = (const float*)d_in[27];

    float* out    = (float*)d_out;
    float* scores = out;
    float* cur1   = out + (size_t)RR * LL;
    float* cur2   = cur1 + (size_t)RR * NN * 64;

    cudaFuncSetAttribute(k_conv, cudaFuncAttributeMaxDynamicSharedMemorySize, 66304);
    cudaFuncSetAttribute(k_gru,  cudaFuncAttributeMaxDynamicSharedMemorySize, 83968);

    dim3 gridL((NN + 127) / 128, RR);
    const int scat_blocks = (RR * EE * 16 + 255) / 256;

    // ---- layer 1 ----
    k_zero<<<18750, 256>>>();
    k_scatter<<<scat_blocks, 256>>>(x, 0, ei);
    k_conv<<<gridL, 128, 66304>>>(x, 0, W1rel, b1rel, W1root);
    k_gru<<<gridL, 128, 83968>>>(past1, g1Wi, g1Wh, g1bi, g1bh, cur1);
    k_att<<<gridL, 128, 16640>>>(cur1, k1W, k1b);
    k_softmax<<<1, 32>>>(q1);
    k_mix<<<(NN * 16 + 255) / 256, 256>>>(cur1);

    // ---- layer 2 ----
    k_zero<<<18750, 256>>>();
    k_scatter<<<scat_blocks, 256>>>(x, 1, ei);   // use_mix=1 -> reads g_mix
    k_conv<<<gridL, 128, 66304>>>(x, 1, W2rel, b2rel, W2root);
    k_gru<<<gridL, 128, 83968>>>(past2, g2Wi, g2Wh, g2bi, g2bh, cur2);
    k_att<<<gridL, 128, 16640>>>(cur2, k2W, k2b);
    k_softmax<<<1, 32>>>(q2);

    // ---- head ----
    k_zfuse<<<(NN + 127) / 128, 128>>>(cur2, postW, postb);
    k_score<<<(RR * LL + 255) / 256, 256>>>(eli, relemb, scores);
}

// round 3
// speedup vs baseline: 2.3684x; 2.3684x over previous
#include <cuda_runtime.h>

#define NN 100000
#define RR 3
#define EE 800000
#define LL 200000

typedef unsigned long long u64t;

// packed f32x2 FMA (sm_100+): d = a*b + c, two fp32 lanes per instruction
__device__ __forceinline__ u64t fma2(u64t a, u64t b, u64t c) {
    u64t d;
    asm("fma.rn.f32x2 %0, %1, %2, %3;" : "=l"(d) : "l"(a), "l"(b), "l"(c));
    return d;
}
__device__ __forceinline__ float lo32(u64t v) { return __uint_as_float((unsigned)v); }
__device__ __forceinline__ float hi32(u64t v) { return __uint_as_float((unsigned)(v >> 32)); }
__device__ __forceinline__ float sum2(u64t v) { return lo32(v) + hi32(v); }

// ---------------- scratch ----------------
__device__ __align__(16) float g_agg[(size_t)RR * NN * 64];
__device__ __align__(16) float g_h[(size_t)RR * NN * 64];
__device__ __align__(16) float g_mix[(size_t)NN * 64];
__device__ __align__(16) float g_z[(size_t)NN * 2];
__device__ float g_score[RR];
__device__ float g_attn[RR];

// ---------------- zero agg buffer + score ----------------
__global__ void k_zero() {
    int i = blockIdx.x * blockDim.x + threadIdx.x;
    const int tot4 = RR * NN * 16;
    if (i < tot4) ((float4*)g_agg)[i] = make_float4(0.f, 0.f, 0.f, 0.f);
    if (i < RR) g_score[i] = 0.f;
}

// ---------------- scatter: agg[r][dst] += feat[src], vectorized red.v4 ----------------
__global__ void k_scatter(const float* __restrict__ feat, int use_mix,
                          const int* __restrict__ ei) {
    unsigned idx = blockIdx.x * blockDim.x + threadIdx.x;
    if (idx >= (unsigned)RR * EE * 16u) return;
    const float* f = use_mix ? g_mix : feat;
    unsigned chunk = idx & 15u;
    unsigned e = idx >> 4;
    unsigned r = e / EE;
    unsigned eo = e - r * EE;
    int s = ei[(size_t)r * 2 * EE + eo];
    int d = ei[(size_t)r * 2 * EE + EE + eo];
    float4 v = *(const float4*)(f + (size_t)s * 64 + chunk * 4);
    float* o = g_agg + ((size_t)r * NN + d) * 64 + chunk * 4;
    asm volatile("red.global.add.v4.f32 [%0], {%1, %2, %3, %4};"
                 :: "l"(o), "f"(v.x), "f"(v.y), "f"(v.z), "f"(v.w) : "memory");
}

// ---------------- graphconv: g_h = relu(agg @ Wrel.T + b + root @ Wroot.T) ----------------
__global__ __launch_bounds__(256) void k_conv(
    const float* __restrict__ root_in, int use_mix,
    const float* __restrict__ Wrel, const float* __restrict__ brel,
    const float* __restrict__ Wroot) {
    extern __shared__ float sm[];
    float* sWa  = sm;          // 4096
    float* sWb  = sm + 4096;   // 4096
    float* sB   = sm + 8192;   // 64
    float* sOut = sm + 8256;   // 256*65
    const int r = blockIdx.y;
    const int tid = threadIdx.x;
    const int node0 = blockIdx.x * 256;
    const int node = min(node0 + tid, NN - 1);
    const float* rp = use_mix ? g_mix : root_in;
    {
        const float4* wr = (const float4*)(Wrel + (size_t)r * 4096);
        const float4* wo = (const float4*)(Wroot + (size_t)r * 4096);
        for (int i = tid; i < 1024; i += 256) {
            ((float4*)sWa)[i] = wr[i];
            ((float4*)sWb)[i] = wo[i];
        }
        if (tid < 64) sB[tid] = brel[r * 64 + tid];
    }
    __syncthreads();

    u64t va[32], vb[32];
    const ulonglong2* ap = (const ulonglong2*)(g_agg + ((size_t)r * NN + node) * 64);
    const ulonglong2* bp = (const ulonglong2*)(rp + (size_t)node * 64);
#pragma unroll
    for (int i = 0; i < 16; i++) {
        ulonglong2 t = ap[i]; va[2*i] = t.x; va[2*i+1] = t.y;
        ulonglong2 u = bp[i]; vb[2*i] = u.x; vb[2*i+1] = u.y;
    }
    for (int c = 0; c < 64; c++) {
        const ulonglong2* wa = (const ulonglong2*)(sWa + c * 64);
        const ulonglong2* wb = (const ulonglong2*)(sWb + c * 64);
        u64t a2 = 0, b2 = 0;
#pragma unroll
        for (int k = 0; k < 16; k++) {
            ulonglong2 w1 = wa[k];
            a2 = fma2(w1.x, va[2*k], a2);
            a2 = fma2(w1.y, va[2*k+1], a2);
            ulonglong2 w2 = wb[k];
            b2 = fma2(w2.x, vb[2*k], b2);
            b2 = fma2(w2.y, vb[2*k+1], b2);
        }
        sOut[tid * 65 + c] = fmaxf(sum2(a2) + sum2(b2) + sB[c], 0.f);
    }
    __syncthreads();
    float* dst = g_h + ((size_t)r * NN + node0) * 64;
    int total = min(256, NN - node0) * 64;
    for (int i = tid; i < total; i += 256)
        dst[i] = sOut[(i >> 6) * 65 + (i & 63)];
}

// ---------------- GRU ----------------
__global__ __launch_bounds__(256) void k_gru(
    const float* __restrict__ past,
    const float* __restrict__ Wi, const float* __restrict__ Wh,
    const float* __restrict__ bi, const float* __restrict__ bh,
    float* __restrict__ cur) {
    extern __shared__ float sm[];
    float* sWi  = sm;            // 12288
    float* sWh  = sm + 12288;    // 12288
    float* sBi  = sm + 24576;    // 192
    float* sBh  = sm + 24768;    // 192
    float* sOut = sm + 24960;    // 256*65
    const int r = blockIdx.y;
    const int tid = threadIdx.x;
    const int node0 = blockIdx.x * 256;
    const int node = min(node0 + tid, NN - 1);
    {
        const float4* wi4 = (const float4*)Wi;
        const float4* wh4 = (const float4*)Wh;
        for (int i = tid; i < 3072; i += 256) {
            ((float4*)sWi)[i] = wi4[i];
            ((float4*)sWh)[i] = wh4[i];
        }
        if (tid < 64) {
            sBi[tid] = bi[tid]; sBi[64+tid] = bi[64+tid]; sBi[128+tid] = bi[128+tid];
            sBh[tid] = bh[tid]; sBh[64+tid] = bh[64+tid]; sBh[128+tid] = bh[128+tid];
        }
    }
    __syncthreads();

    u64t h2[32], pv2[32];
    const ulonglong2* hp = (const ulonglong2*)(g_h + ((size_t)r * NN + node) * 64);
    const ulonglong2* pp = (const ulonglong2*)(past + ((size_t)r * NN + node) * 64);
#pragma unroll
    for (int i = 0; i < 16; i++) {
        ulonglong2 t = hp[i]; h2[2*i]  = t.x; h2[2*i+1]  = t.y;
        ulonglong2 u = pp[i]; pv2[2*i] = u.x; pv2[2*i+1] = u.y;
    }
    for (int c = 0; c < 64; c++) {
        const ulonglong2* wir = (const ulonglong2*)(sWi + c * 64);
        const ulonglong2* wiz = (const ulonglong2*)(sWi + (64 + c) * 64);
        const ulonglong2* win = (const ulonglong2*)(sWi + (128 + c) * 64);
        const ulonglong2* whr = (const ulonglong2*)(sWh + c * 64);
        const ulonglong2* whz = (const ulonglong2*)(sWh + (64 + c) * 64);
        const ulonglong2* whn = (const ulonglong2*)(sWh + (128 + c) * 64);
        u64t gir = 0, giz = 0, gin = 0, ghr = 0, ghz = 0, ghn = 0;
#pragma unroll
        for (int k = 0; k < 16; k++) {
            ulonglong2 w0 = wir[k]; gir = fma2(w0.x, h2[2*k], gir); gir = fma2(w0.y, h2[2*k+1], gir);
            ulonglong2 w1 = wiz[k]; giz = fma2(w1.x, h2[2*k], giz); giz = fma2(w1.y, h2[2*k+1], giz);
            ulonglong2 w2 = win[k]; gin = fma2(w2.x, h2[2*k], gin); gin = fma2(w2.y, h2[2*k+1], gin);
            ulonglong2 w3 = whr[k]; ghr = fma2(w3.x, pv2[2*k], ghr); ghr = fma2(w3.y, pv2[2*k+1], ghr);
            ulonglong2 w4 = whz[k]; ghz = fma2(w4.x, pv2[2*k], ghz); ghz = fma2(w4.y, pv2[2*k+1], ghz);
            ulonglong2 w5 = whn[k]; ghn = fma2(w5.x, pv2[2*k], ghn); ghn = fma2(w5.y, pv2[2*k+1], ghn);
        }
        float rg = 1.f / (1.f + __expf(-(sBi[c] + sum2(gir) + sBh[c] + sum2(ghr))));
        float zg = 1.f / (1.f + __expf(-(sBi[64+c] + sum2(giz) + sBh[64+c] + sum2(ghz))));
        float hn = sBh[128+c] + sum2(ghn);
        float ng = tanhf(sBi[128+c] + sum2(gin) + rg * hn);
        float p  = (c & 1) ? hi32(pv2[c >> 1]) : lo32(pv2[c >> 1]);
        sOut[tid * 65 + c] = (1.f - zg) * ng + zg * p;
    }
    __syncthreads();
    float* dst = cur + ((size_t)r * NN + node0) * 64;
    int total = min(256, NN - node0) * 64;
    for (int i = tid; i < total; i += 256)
        dst[i] = sOut[(i >> 6) * 65 + (i & 63)];
}

// ---------------- semantic attention: g_score[r] += sum_node sum_c q[c]*tanh((cur@kW.T+kb)[c]) ----------------
__global__ __launch_bounds__(256) void k_att(
    const float* __restrict__ cur, const float* __restrict__ kW,
    const float* __restrict__ kb, const float* __restrict__ q) {
    extern __shared__ float sm[];
    float* sW = sm;          // 4096
    float* sb = sm + 4096;   // 64
    float* sq = sm + 4160;   // 64
    float* sred = sm + 4224; // 8
    const int r = blockIdx.y;
    const int tid = threadIdx.x;
    const int noden = blockIdx.x * 256 + tid;
    const bool act = noden < NN;
    const int node = act ? noden : NN - 1;
    for (int i = tid; i < 1024; i += 256) ((float4*)sW)[i] = ((const float4*)kW)[i];
    if (tid < 64) { sb[tid] = kb[tid]; sq[tid] = q[tid]; }
    __syncthreads();

    u64t cv2[32];
    const ulonglong2* cp = (const ulonglong2*)(cur + ((size_t)r * NN + node) * 64);
#pragma unroll
    for (int i = 0; i < 16; i++) {
        ulonglong2 t = cp[i]; cv2[2*i] = t.x; cv2[2*i+1] = t.y;
    }
    float acc = 0.f;
    for (int c = 0; c < 64; c++) {
        const ulonglong2* w = (const ulonglong2*)(sW + c * 64);
        u64t a2 = 0;
#pragma unroll
        for (int k = 0; k < 16; k++) {
            ulonglong2 ww = w[k];
            a2 = fma2(ww.x, cv2[2*k], a2);
            a2 = fma2(ww.y, cv2[2*k+1], a2);
        }
        acc += sq[c] * tanhf(sum2(a2) + sb[c]);
    }
    if (!act) acc = 0.f;
#pragma unroll
    for (int o = 16; o; o >>= 1) acc += __shfl_down_sync(0xffffffffu, acc, o);
    int warp = tid >> 5;
    if ((tid & 31) == 0) sred[warp] = acc;
    __syncthreads();
    if (tid == 0) {
        float t = 0.f;
#pragma unroll
        for (int i = 0; i < 8; i++) t += sred[i];
        atomicAdd(&g_score[r], t);
    }
}

// ---------------- softmax over relations ----------------
__global__ void k_softmax() {
    if (threadIdx.x == 0) {
        const float inv = 1.0f / (float)NN;
        float s0 = g_score[0] * inv, s1 = g_score[1] * inv, s2 = g_score[2] * inv;
        float m = fmaxf(s0, fmaxf(s1, s2));
        float e0 = __expf(s0 - m), e1 = __expf(s1 - m), e2 = __expf(s2 - m);
        float d = 1.f / (e0 + e1 + e2);
        g_attn[0] = e0 * d; g_attn[1] = e1 * d; g_attn[2] = e2 * d;
    }
}

// ---------------- attention mix ----------------
__global__ void k_mix(const float* __restrict__ cur) {
    int i = blockIdx.x * blockDim.x + threadIdx.x;
    if (i >= NN * 16) return;
    float a0 = g_attn[0], a1 = g_attn[1], a2 = g_attn[2];
    const float4* c = (const float4*)cur;
    float4 v0 = c[i], v1 = c[i + (size_t)NN * 16], v2 = c[i + (size_t)2 * NN * 16];
    float4 o;
    o.x = a0*v0.x + a1*v1.x + a2*v2.x;
    o.y = a0*v0.y + a1*v1.y + a2*v2.y;
    o.z = a0*v0.z + a1*v1.z + a2*v2.z;
    o.w = a0*v0.w + a1*v1.w + a2*v2.w;
    ((float4*)g_mix)[i] = o;
}

// ---------------- final projection ----------------
__global__ __launch_bounds__(128) void k_zfuse(
    const float* __restrict__ cur2, const float* __restrict__ postW,
    const float* __restrict__ postb) {
    int node = blockIdx.x * blockDim.x + threadIdx.x;
    if (node >= NN) return;
    float a0 = g_attn[0], a1 = g_attn[1], a2 = g_attn[2];
    const float4* c0 = (const float4*)(cur2 + (size_t)node * 64);
    const float4* c1 = (const float4*)(cur2 + ((size_t)NN + node) * 64);
    const float4* c2 = (const float4*)(cur2 + ((size_t)2 * NN + node) * 64);
    const float4* w0 = (const float4*)postW;
    const float4* w1 = (const float4*)(postW + 64);
    float z0 = postb[0], z1 = postb[1];
#pragma unroll
    for (int i = 0; i < 16; i++) {
        float4 u0 = c0[i], u1 = c1[i], u2 = c2[i];
        float4 m;
        m.x = a0*u0.x + a1*u1.x + a2*u2.x;
        m.y = a0*u0.y + a1*u1.y + a2*u2.y;
        m.z = a0*u0.z + a1*u1.z + a2*u2.z;
        m.w = a0*u0.w + a1*u1.w + a2*u2.w;
        float4 p0 = w0[i], p1 = w1[i];
        z0 += m.x*p0.x + m.y*p0.y + m.z*p0.z + m.w*p0.w;
        z1 += m.x*p1.x + m.y*p1.y + m.z*p1.z + m.w*p1.w;
    }
    g_z[2 * node]     = z0;
    g_z[2 * node + 1] = z1;
}

// ---------------- link scores ----------------
__global__ void k_score(const int* __restrict__ eli, const float* __restrict__ rel,
                        float* __restrict__ scores) {
    int idx = blockIdx.x * blockDim.x + threadIdx.x;
    if (idx >= RR * LL) return;
    int r = idx / LL;
    int l = idx - r * LL;
    int hd = eli[(size_t)r * 2 * LL + l];
    int tl = eli[(size_t)r * 2 * LL + LL + l];
    float hr = g_z[2 * hd], hi = g_z[2 * hd + 1];
    float tr = g_z[2 * tl], ti = g_z[2 * tl + 1];
    float rr = rel[2 * r], ri = rel[2 * r + 1];
    scores[idx] = hr * rr * tr + hi * rr * ti + hr * ri * ti - hi * ri * tr;
}

// ---------------- host ----------------
extern "C" void kernel_launch(void* const* d_in, const int* in_sizes, int n_in,
                              void* d_out, int out_size) {
    const float* x      = (const float*)d_in[0];
    const int*   ei     = (const int*)d_in[1];
    const int*   eli    = (const int*)d_in[2];
    const float* past1  = (const float*)d_in[3];
    const float* past2  = (const float*)d_in[4];
    const float* W1rel  = (const float*)d_in[5];
    const float* b1rel  = (const float*)d_in[6];
    const float* W1root = (const float*)d_in[7];
    const float* g1Wi   = (const float*)d_in[8];
    const float* g1Wh   = (const float*)d_in[9];
    const float* g1bi   = (const float*)d_in[10];
    const float* g1bh   = (const float*)d_in[11];
    const float* k1W    = (const float*)d_in[12];
    const float* k1b    = (const float*)d_in[13];
    const float* q1     = (const float*)d_in[14];
    const float* W2rel  = (const float*)d_in[15];
    const float* b2rel  = (const float*)d_in[16];
    const float* W2root = (const float*)d_in[17];
    const float* g2Wi   = (const float*)d_in[18];
    const float* g2Wh   = (const float*)d_in[19];
    const float* g2bi   = (const float*)d_in[20];
    const float* g2bh   = (const float*)d_in[21];
    const float* k2W    = (const float*)d_in[22];
    const float* k2b    = (const float*)d_in[23];
    const float* q2     = (const float*)d_in[24];
    const float* postW  = (const float*)d_in[25];
    const float* postb  = (const float*)d_in[26];
    const float* relemb = (const float*)d_in[27];

    float* out    = (float*)d_out;
    float* scores = out;
    float* cur1   = out + (size_t)RR * LL;
    float* cur2   = cur1 + (size_t)RR * NN * 64;

    const int CONV_SMEM = (8256 + 256 * 65) * 4;          // 99584 B
    const int GRU_SMEM  = (24960 + 256 * 65) * 4;         // 166400 B
    const int ATT_SMEM  = 4232 * 4;                       // 16928 B
    cudaFuncSetAttribute(k_conv, cudaFuncAttributeMaxDynamicSharedMemorySize, CONV_SMEM);
    cudaFuncSetAttribute(k_gru,  cudaFuncAttributeMaxDynamicSharedMemorySize, GRU_SMEM);

    dim3 gridL((NN + 255) / 256, RR);
    const int scat_blocks = (RR * EE * 16 + 255) / 256;

    // ---- layer 1 ----
    k_zero<<<18750, 256>>>();
    k_scatter<<<scat_blocks, 256>>>(x, 0, ei);
    k_conv<<<gridL, 256, CONV_SMEM>>>(x, 0, W1rel, b1rel, W1root);
    k_gru<<<gridL, 256, GRU_SMEM>>>(past1, g1Wi, g1Wh, g1bi, g1bh, cur1);
    k_att<<<gridL, 256, ATT_SMEM>>>(cur1, k1W, k1b, q1);
    k_softmax<<<1, 32>>>();
    k_mix<<<(NN * 16 + 255) / 256, 256>>>(cur1);

    // ---- layer 2 ----
    k_zero<<<18750, 256>>>();
    k_scatter<<<scat_blocks, 256>>>(x, 1, ei);
    k_conv<<<gridL, 256, CONV_SMEM>>>(x, 1, W2rel, b2rel, W2root);
    k_gru<<<gridL, 256, GRU_SMEM>>>(past2, g2Wi, g2Wh, g2bi, g2bh, cur2);
    k_att<<<gridL, 256, ATT_SMEM>>>(cur2, k2W, k2b, q2);
    k_softmax<<<1, 32>>>();

    // ---- head ----
    k_zfuse<<<(NN + 127) / 128, 128>>>(cur2, postW, postb);
    k_score<<<(RR * LL + 255) / 256, 256>>>(eli, relemb, scores);
}

// round 4
// speedup vs baseline: 2.7358x; 1.1552x over previous
#include <cuda_runtime.h>

#define NN 100000
#define RR 3
#define EE 800000
#define LL 200000
#define PAD 68   // SMEM row stride (words) for 64-wide rows: 68 mod 32 = 4 -> conflict-free

// ---------------- scratch ----------------
__device__ __align__(16) float g_agg[(size_t)RR * NN * 64];
__device__ __align__(16) float g_h[(size_t)RR * NN * 64];
__device__ __align__(16) float g_mix[(size_t)NN * 64];
__device__ __align__(16) float g_z[(size_t)NN * 2];
__device__ float g_score[RR];
__device__ float g_attn[RR];

// ---------------- tf32 helpers ----------------
__device__ __forceinline__ void tfsplit(float v, unsigned& b, unsigned& s) {
    asm("cvt.rna.tf32.f32 %0, %1;" : "=r"(b) : "f"(v));
    float res = v - __uint_as_float(b);
    asm("cvt.rna.tf32.f32 %0, %1;" : "=r"(s) : "f"(res));
}
__device__ __forceinline__ void mma_tf32(float* d, const unsigned* a, const unsigned* b) {
    asm volatile(
        "mma.sync.aligned.m16n8k8.row.col.f32.tf32.tf32.f32 "
        "{%0,%1,%2,%3},{%4,%5,%6,%7},{%8,%9},{%0,%1,%2,%3};"
        : "+f"(d[0]), "+f"(d[1]), "+f"(d[2]), "+f"(d[3])
        : "r"(a[0]), "r"(a[1]), "r"(a[2]), "r"(a[3]), "r"(b[0]), "r"(b[1]));
}
// load A fragment (16x8) from padded SMEM tile and split into big/small tf32
__device__ __forceinline__ void load_afrag(const float* tile, int wn0, int g, int t, int ks,
                                           unsigned* ab, unsigned* as) {
    int col = ks * 8 + t;
    float a0 = tile[(wn0 + g) * PAD + col];
    float a1 = tile[(wn0 + g + 8) * PAD + col];
    float a2 = tile[(wn0 + g) * PAD + col + 4];
    float a3 = tile[(wn0 + g + 8) * PAD + col + 4];
    tfsplit(a0, ab[0], as[0]);
    tfsplit(a1, ab[1], as[1]);
    tfsplit(a2, ab[2], as[2]);
    tfsplit(a3, ab[3], as[3]);
}
// load B fragment (8x8, col-major = W[c][k] rows) from padded SMEM and split
__device__ __forceinline__ void load_bfrag(const float* wtile, int c0, int g, int t, int ks,
                                           unsigned* bb, unsigned* bs) {
    int k0 = ks * 8 + t;
    float v0 = wtile[(c0 + g) * PAD + k0];
    float v1 = wtile[(c0 + g) * PAD + k0 + 4];
    tfsplit(v0, bb[0], bs[0]);
    tfsplit(v1, bb[1], bs[1]);
}

// ---------------- zero agg buffer + score ----------------
__global__ void k_zero() {
    int i = blockIdx.x * blockDim.x + threadIdx.x;
    const int tot4 = RR * NN * 16;
    if (i < tot4) ((float4*)g_agg)[i] = make_float4(0.f, 0.f, 0.f, 0.f);
    if (i < RR) g_score[i] = 0.f;
}

// ---------------- scatter: agg[r][dst] += feat[src], red.v4 ----------------
__global__ void k_scatter(const float* __restrict__ feat, int use_mix,
                          const int* __restrict__ ei) {
    unsigned idx = blockIdx.x * blockDim.x + threadIdx.x;
    if (idx >= (unsigned)RR * EE * 16u) return;
    const float* f = use_mix ? g_mix : feat;
    unsigned chunk = idx & 15u;
    unsigned e = idx >> 4;
    unsigned r = e / EE;
    unsigned eo = e - r * EE;
    int s = ei[(size_t)r * 2 * EE + eo];
    int d = ei[(size_t)r * 2 * EE + EE + eo];
    float4 v = *(const float4*)(f + (size_t)s * 64 + chunk * 4);
    float* o = g_agg + ((size_t)r * NN + d) * 64 + chunk * 4;
    asm volatile("red.global.add.v4.f32 [%0], {%1, %2, %3, %4};"
                 :: "l"(o), "f"(v.x), "f"(v.y), "f"(v.z), "f"(v.w) : "memory");
}

// ---------------- graphconv (tensor cores): g_h = relu(agg@Wrel.T + b + root@Wroot.T) ----------------
__global__ __launch_bounds__(256, 1) void k_conv(
    const float* __restrict__ root_in, int use_mix,
    const float* __restrict__ Wrel, const float* __restrict__ brel,
    const float* __restrict__ Wroot) {
    extern __shared__ float sm[];
    float* sWa = sm;                   // 64*PAD
    float* sWb = sWa + 64 * PAD;       // 64*PAD
    float* sA  = sWb + 64 * PAD;       // 128*PAD (agg)
    float* sR  = sA + 128 * PAD;       // 128*PAD (root)
    float* sB  = sR + 128 * PAD;       // 64
    const int r = blockIdx.y, tid = threadIdx.x;
    const int node0 = blockIdx.x * 128;
    const float* rp = use_mix ? g_mix : root_in;

    for (int i = tid; i < 64 * 16; i += 256) {
        int row = i >> 4, c4 = (i & 15) << 2;
        *(float4*)(sWa + row * PAD + c4) = *(const float4*)(Wrel + (size_t)r * 4096 + row * 64 + c4);
        *(float4*)(sWb + row * PAD + c4) = *(const float4*)(Wroot + (size_t)r * 4096 + row * 64 + c4);
    }
    if (tid < 64) sB[tid] = brel[r * 64 + tid];
    for (int i = tid; i < 128 * 16; i += 256) {
        int row = i >> 4, c4 = (i & 15) << 2;
        int node = min(node0 + row, NN - 1);
        *(float4*)(sA + row * PAD + c4) = *(const float4*)(g_agg + ((size_t)r * NN + node) * 64 + c4);
        *(float4*)(sR + row * PAD + c4) = *(const float4*)(rp + (size_t)node * 64 + c4);
    }
    __syncthreads();

    int lane = tid & 31, warp = tid >> 5;
    int g = lane >> 2, t = lane & 3;
    int wn0 = warp * 16;

    unsigned ab_[32], as_[32], rb_[32], rs_[32];
#pragma unroll
    for (int ks = 0; ks < 8; ks++) {
        load_afrag(sA, wn0, g, t, ks, ab_ + ks * 4, as_ + ks * 4);
        load_afrag(sR, wn0, g, t, ks, rb_ + ks * 4, rs_ + ks * 4);
    }

    for (int j = 0; j < 8; j++) {
        float acc0[4] = {0.f, 0.f, 0.f, 0.f};
        float acc1[4] = {0.f, 0.f, 0.f, 0.f};
#pragma unroll
        for (int ks = 0; ks < 8; ks++) {
            unsigned bb0[2], bs0[2], bb1[2], bs1[2];
            load_bfrag(sWa, j * 8, g, t, ks, bb0, bs0);
            load_bfrag(sWb, j * 8, g, t, ks, bb1, bs1);
            mma_tf32(acc0, ab_ + ks * 4, bb0);
            mma_tf32(acc1, rb_ + ks * 4, bb1);
            mma_tf32(acc0, ab_ + ks * 4, bs0);
            mma_tf32(acc1, rb_ + ks * 4, bs1);
            mma_tf32(acc0, as_ + ks * 4, bb0);
            mma_tf32(acc1, rs_ + ks * 4, bb1);
        }
#pragma unroll
        for (int e = 0; e < 4; e++) {
            int row = wn0 + g + ((e & 2) ? 8 : 0);
            int node = node0 + row;
            int c = j * 8 + t * 2 + (e & 1);
            if (node < NN)
                g_h[((size_t)r * NN + node) * 64 + c] = fmaxf(acc0[e] + acc1[e] + sB[c], 0.f);
        }
    }
}

// ---------------- GRU (tensor cores) ----------------
__global__ __launch_bounds__(256, 1) void k_gru(
    const float* __restrict__ past,
    const float* __restrict__ Wi, const float* __restrict__ Wh,
    const float* __restrict__ bi, const float* __restrict__ bh,
    float* __restrict__ cur) {
    extern __shared__ float sm[];
    float* sWi = sm;                    // 192*PAD
    float* sWh = sWi + 192 * PAD;       // 192*PAD
    float* sH  = sWh + 192 * PAD;       // 128*PAD
    float* sP  = sH + 128 * PAD;        // 128*PAD
    float* sBi = sP + 128 * PAD;        // 192
    float* sBh = sBi + 192;             // 192
    const int r = blockIdx.y, tid = threadIdx.x;
    const int node0 = blockIdx.x * 128;

    for (int i = tid; i < 192 * 16; i += 256) {
        int row = i >> 4, c4 = (i & 15) << 2;
        *(float4*)(sWi + row * PAD + c4) = *(const float4*)(Wi + row * 64 + c4);
        *(float4*)(sWh + row * PAD + c4) = *(const float4*)(Wh + row * 64 + c4);
    }
    if (tid < 192) { sBi[tid] = bi[tid]; sBh[tid] = bh[tid]; }
    for (int i = tid; i < 128 * 16; i += 256) {
        int row = i >> 4, c4 = (i & 15) << 2;
        int node = min(node0 + row, NN - 1);
        *(float4*)(sH + row * PAD + c4) = *(const float4*)(g_h + ((size_t)r * NN + node) * 64 + c4);
        *(float4*)(sP + row * PAD + c4) = *(const float4*)(past + ((size_t)r * NN + node) * 64 + c4);
    }
    __syncthreads();

    int lane = tid & 31, warp = tid >> 5;
    int g = lane >> 2, t = lane & 3;
    int wn0 = warp * 16;

    unsigned hb[32], hs[32], pb[32], ps[32];
#pragma unroll
    for (int ks = 0; ks < 8; ks++) {
        load_afrag(sH, wn0, g, t, ks, hb + ks * 4, hs + ks * 4);
        load_afrag(sP, wn0, g, t, ks, pb + ks * 4, ps + ks * 4);
    }

    for (int j = 0; j < 8; j++) {
        float acc[6][4] = {};  // ir, iz, in, hr, hz, hn
#pragma unroll
        for (int ks = 0; ks < 8; ks++) {
            unsigned bb[6][2], bs[6][2];
#pragma unroll
            for (int m = 0; m < 3; m++) {
                load_bfrag(sWi, m * 64 + j * 8, g, t, ks, bb[m], bs[m]);
                load_bfrag(sWh, m * 64 + j * 8, g, t, ks, bb[3 + m], bs[3 + m]);
            }
            const unsigned* Hb = hb + ks * 4;
            const unsigned* Hs = hs + ks * 4;
            const unsigned* Pb = pb + ks * 4;
            const unsigned* Ps = ps + ks * 4;
            // term 1: big*big
            mma_tf32(acc[0], Hb, bb[0]); mma_tf32(acc[1], Hb, bb[1]); mma_tf32(acc[2], Hb, bb[2]);
            mma_tf32(acc[3], Pb, bb[3]); mma_tf32(acc[4], Pb, bb[4]); mma_tf32(acc[5], Pb, bb[5]);
            // term 2: big*small
            mma_tf32(acc[0], Hb, bs[0]); mma_tf32(acc[1], Hb, bs[1]); mma_tf32(acc[2], Hb, bs[2]);
            mma_tf32(acc[3], Pb, bs[3]); mma_tf32(acc[4], Pb, bs[4]); mma_tf32(acc[5], Pb, bs[5]);
            // term 3: small*big
            mma_tf32(acc[0], Hs, bb[0]); mma_tf32(acc[1], Hs, bb[1]); mma_tf32(acc[2], Hs, bb[2]);
            mma_tf32(acc[3], Ps, bb[3]); mma_tf32(acc[4], Ps, bb[4]); mma_tf32(acc[5], Ps, bb[5]);
        }
#pragma unroll
        for (int e = 0; e < 4; e++) {
            int row = wn0 + g + ((e & 2) ? 8 : 0);
            int node = node0 + row;
            int c = j * 8 + t * 2 + (e & 1);
            float gir = acc[0][e] + sBi[c];
            float giz = acc[1][e] + sBi[64 + c];
            float gin = acc[2][e] + sBi[128 + c];
            float ghr = acc[3][e] + sBh[c];
            float ghz = acc[4][e] + sBh[64 + c];
            float ghn = acc[5][e] + sBh[128 + c];
            float rg = 1.f / (1.f + __expf(-(gir + ghr)));
            float zg = 1.f / (1.f + __expf(-(giz + ghz)));
            float ng = tanhf(gin + rg * ghn);
            float p = sP[row * PAD + c];
            if (node < NN)
                cur[((size_t)r * NN + node) * 64 + c] = (1.f - zg) * ng + zg * p;
        }
    }
}

// ---------------- semantic attention (tensor cores): g_score[r] += sum q[c]*tanh((cur@kW.T+kb)[c]) ----------------
__global__ __launch_bounds__(256, 1) void k_att(
    const float* __restrict__ cur, const float* __restrict__ kW,
    const float* __restrict__ kb, const float* __restrict__ q) {
    extern __shared__ float sm[];
    float* sW = sm;                    // 64*PAD
    float* sC = sW + 64 * PAD;         // 128*PAD
    float* sb = sC + 128 * PAD;        // 64
    float* sq = sb + 64;               // 64
    const int r = blockIdx.y, tid = threadIdx.x;
    const int node0 = blockIdx.x * 128;

    for (int i = tid; i < 64 * 16; i += 256) {
        int row = i >> 4, c4 = (i & 15) << 2;
        *(float4*)(sW + row * PAD + c4) = *(const float4*)(kW + row * 64 + c4);
    }
    if (tid < 64) { sb[tid] = kb[tid]; sq[tid] = q[tid]; }
    for (int i = tid; i < 128 * 16; i += 256) {
        int row = i >> 4, c4 = (i & 15) << 2;
        int node = min(node0 + row, NN - 1);
        *(float4*)(sC + row * PAD + c4) = *(const float4*)(cur + ((size_t)r * NN + node) * 64 + c4);
    }
    __syncthreads();

    int lane = tid & 31, warp = tid >> 5;
    int g = lane >> 2, t = lane & 3;
    int wn0 = warp * 16;

    unsigned cb[32], cs[32];
#pragma unroll
    for (int ks = 0; ks < 8; ks++)
        load_afrag(sC, wn0, g, t, ks, cb + ks * 4, cs + ks * 4);

    float ssum = 0.f;
    for (int j = 0; j < 8; j++) {
        float acc[4] = {0.f, 0.f, 0.f, 0.f};
#pragma unroll
        for (int ks = 0; ks < 8; ks++) {
            unsigned bb[2], bs[2];
            load_bfrag(sW, j * 8, g, t, ks, bb, bs);
            mma_tf32(acc, cb + ks * 4, bb);
            mma_tf32(acc, cb + ks * 4, bs);
            mma_tf32(acc, cs + ks * 4, bb);
        }
#pragma unroll
        for (int e = 0; e < 4; e++) {
            int row = wn0 + g + ((e & 2) ? 8 : 0);
            int node = node0 + row;
            int c = j * 8 + t * 2 + (e & 1);
            if (node < NN) ssum += sq[c] * tanhf(acc[e] + sb[c]);
        }
    }
#pragma unroll
    for (int o = 16; o; o >>= 1) ssum += __shfl_down_sync(0xffffffffu, ssum, o);
    if (lane == 0) atomicAdd(&g_score[r], ssum);
}

// ---------------- softmax over relations ----------------
__global__ void k_softmax() {
    if (threadIdx.x == 0) {
        const float inv = 1.0f / (float)NN;
        float s0 = g_score[0] * inv, s1 = g_score[1] * inv, s2 = g_score[2] * inv;
        float m = fmaxf(s0, fmaxf(s1, s2));
        float e0 = __expf(s0 - m), e1 = __expf(s1 - m), e2 = __expf(s2 - m);
        float d = 1.f / (e0 + e1 + e2);
        g_attn[0] = e0 * d; g_attn[1] = e1 * d; g_attn[2] = e2 * d;
    }
}

// ---------------- attention mix ----------------
__global__ void k_mix(const float* __restrict__ cur) {
    int i = blockIdx.x * blockDim.x + threadIdx.x;
    if (i >= NN * 16) return;
    float a0 = g_attn[0], a1 = g_attn[1], a2 = g_attn[2];
    const float4* c = (const float4*)cur;
    float4 v0 = c[i], v1 = c[i + (size_t)NN * 16], v2 = c[i + (size_t)2 * NN * 16];
    float4 o;
    o.x = a0*v0.x + a1*v1.x + a2*v2.x;
    o.y = a0*v0.y + a1*v1.y + a2*v2.y;
    o.z = a0*v0.z + a1*v1.z + a2*v2.z;
    o.w = a0*v0.w + a1*v1.w + a2*v2.w;
    ((float4*)g_mix)[i] = o;
}

// ---------------- final projection ----------------
__global__ __launch_bounds__(128) void k_zfuse(
    const float* __restrict__ cur2, const float* __restrict__ postW,
    const float* __restrict__ postb) {
    int node = blockIdx.x * blockDim.x + threadIdx.x;
    if (node >= NN) return;
    float a0 = g_attn[0], a1 = g_attn[1], a2 = g_attn[2];
    const float4* c0 = (const float4*)(cur2 + (size_t)node * 64);
    const float4* c1 = (const float4*)(cur2 + ((size_t)NN + node) * 64);
    const float4* c2 = (const float4*)(cur2 + ((size_t)2 * NN + node) * 64);
    const float4* w0 = (const float4*)postW;
    const float4* w1 = (const float4*)(postW + 64);
    float z0 = postb[0], z1 = postb[1];
#pragma unroll
    for (int i = 0; i < 16; i++) {
        float4 u0 = c0[i], u1 = c1[i], u2 = c2[i];
        float4 m;
        m.x = a0*u0.x + a1*u1.x + a2*u2.x;
        m.y = a0*u0.y + a1*u1.y + a2*u2.y;
        m.z = a0*u0.z + a1*u1.z + a2*u2.z;
        m.w = a0*u0.w + a1*u1.w + a2*u2.w;
        float4 p0 = w0[i], p1 = w1[i];
        z0 += m.x*p0.x + m.y*p0.y + m.z*p0.z + m.w*p0.w;
        z1 += m.x*p1.x + m.y*p1.y + m.z*p1.z + m.w*p1.w;
    }
    g_z[2 * node]     = z0;
    g_z[2 * node + 1] = z1;
}

// ---------------- link scores ----------------
__global__ void k_score(const int* __restrict__ eli, const float* __restrict__ rel,
                        float* __restrict__ scores) {
    int idx = blockIdx.x * blockDim.x + threadIdx.x;
    if (idx >= RR * LL) return;
    int r = idx / LL;
    int l = idx - r * LL;
    int hd = eli[(size_t)r * 2 * LL + l];
    int tl = eli[(size_t)r * 2 * LL + LL + l];
    float hr = g_z[2 * hd], hi = g_z[2 * hd + 1];
    float tr = g_z[2 * tl], ti = g_z[2 * tl + 1];
    float rr = rel[2 * r], ri = rel[2 * r + 1];
    scores[idx] = hr * rr * tr + hi * rr * ti + hr * ri * ti - hi * ri * tr;
}

// ---------------- host ----------------
extern "C" void kernel_launch(void* const* d_in, const int* in_sizes, int n_in,
                              void* d_out, int out_size) {
    const float* x      = (const float*)d_in[0];
    const int*   ei     = (const int*)d_in[1];
    const int*   eli    = (const int*)d_in[2];
    const float* past1  = (const float*)d_in[3];
    const float* past2  = (const float*)d_in[4];
    const float* W1rel  = (const float*)d_in[5];
    const float* b1rel  = (const float*)d_in[6];
    const float* W1root = (const float*)d_in[7];
    const float* g1Wi   = (const float*)d_in[8];
    const float* g1Wh   = (const float*)d_in[9];
    const float* g1bi   = (const float*)d_in[10];
    const float* g1bh   = (const float*)d_in[11];
    const float* k1W    = (const float*)d_in[12];
    const float* k1b    = (const float*)d_in[13];
    const float* q1     = (const float*)d_in[14];
    const float* W2rel  = (const float*)d_in[15];
    const float* b2rel  = (const float*)d_in[16];
    const float* W2root = (const float*)d_in[17];
    const float* g2Wi   = (const float*)d_in[18];
    const float* g2Wh   = (const float*)d_in[19];
    const float* g2bi   = (const float*)d_in[20];
    const float* g2bh   = (const float*)d_in[21];
    const float* k2W    = (const float*)d_in[22];
    const float* k2b    = (const float*)d_in[23];
    const float* q2     = (const float*)d_in[24];
    const float* postW  = (const float*)d_in[25];
    const float* postb  = (const float*)d_in[26];
    const float* relemb = (const float*)d_in[27];

    float* out    = (float*)d_out;
    float* scores = out;
    float* cur1   = out + (size_t)RR * LL;
    float* cur2   = cur1 + (size_t)RR * NN * 64;

    const int CONV_SMEM = (64 * PAD * 2 + 128 * PAD * 2 + 64) * 4;       // 104960 B
    const int GRU_SMEM  = (192 * PAD * 2 + 128 * PAD * 2 + 384) * 4;     // 175616 B
    const int ATT_SMEM  = (64 * PAD + 128 * PAD + 128) * 4;              // 52736 B
    cudaFuncSetAttribute(k_conv, cudaFuncAttributeMaxDynamicSharedMemorySize, CONV_SMEM);
    cudaFuncSetAttribute(k_gru,  cudaFuncAttributeMaxDynamicSharedMemorySize, GRU_SMEM);
    cudaFuncSetAttribute(k_att,  cudaFuncAttributeMaxDynamicSharedMemorySize, ATT_SMEM);

    dim3 gridL((NN + 127) / 128, RR);   // 782 x 3
    const int scat_blocks = (RR * EE * 16 + 255) / 256;

    // ---- layer 1 ----
    k_zero<<<18750, 256>>>();
    k_scatter<<<scat_blocks, 256>>>(x, 0, ei);
    k_conv<<<gridL, 256, CONV_SMEM>>>(x, 0, W1rel, b1rel, W1root);
    k_gru<<<gridL, 256, GRU_SMEM>>>(past1, g1Wi, g1Wh, g1bi, g1bh, cur1);
    k_att<<<gridL, 256, ATT_SMEM>>>(cur1, k1W, k1b, q1);
    k_softmax<<<1, 32>>>();
    k_mix<<<(NN * 16 + 255) / 256, 256>>>(cur1);

    // ---- layer 2 ----
    k_zero<<<18750, 256>>>();
    k_scatter<<<scat_blocks, 256>>>(x, 1, ei);
    k_conv<<<gridL, 256, CONV_SMEM>>>(x, 1, W2rel, b2rel, W2root);
    k_gru<<<gridL, 256, GRU_SMEM>>>(past2, g2Wi, g2Wh, g2bi, g2bh, cur2);
    k_att<<<gridL, 256, ATT_SMEM>>>(cur2, k2W, k2b, q2);
    k_softmax<<<1, 32>>>();

    // ---- head ----
    k_zfuse<<<(NN + 127) / 128, 128>>>(cur2, postW, postb);
    k_score<<<(RR * LL + 255) / 256, 256>>>(eli, relemb, scores);
}

// round 5
// speedup vs baseline: 4.4969x; 1.6437x over previous
#include <cuda_runtime.h>

#define NN 100000
#define RR 3
#define EE 800000
#define LL 200000

// ---------------- scratch ----------------
__device__ __align__(16) float g_agg[(size_t)RR * NN * 64];
__device__ __align__(16) float g_h[(size_t)RR * NN * 64];
__device__ __align__(16) float g_mix[(size_t)NN * 64];
__device__ __align__(16) float g_z[(size_t)NN * 2];
__device__ float g_score[RR];
__device__ float g_attn[RR];

// pre-split weight fragments (bf16 big/small, MMA B-fragment order)
// REL: 3*1024, ROOT: 3*1024, WI: 3072, WH: 3072, ATT: 1024
#define WF_REL  0
#define WF_ROOT 3072
#define WF_WI   6144
#define WF_WH   9216
#define WF_ATT  12288
__device__ __align__(16) uint4 g_wfrag[13312];

// ---------------- bf16 helpers ----------------
__device__ __forceinline__ unsigned pack_bf2(float lo, float hi) {
    unsigned d;
    asm("cvt.rn.bf16x2.f32 %0, %1, %2;" : "=r"(d) : "f"(hi), "f"(lo));
    return d;
}
__device__ __forceinline__ float bf_lo(unsigned v) { return __uint_as_float(v << 16); }
__device__ __forceinline__ float bf_hi(unsigned v) { return __uint_as_float(v & 0xffff0000u); }
__device__ __forceinline__ void split2(float2 v, unsigned& big, unsigned& small) {
    big = pack_bf2(v.x, v.y);
    small = pack_bf2(v.x - bf_lo(big), v.y - bf_hi(big));
}
__device__ __forceinline__ void mma_bf(float* d, const unsigned* a, unsigned b0, unsigned b1) {
    asm volatile(
        "mma.sync.aligned.m16n8k16.row.col.f32.bf16.bf16.f32 "
        "{%0,%1,%2,%3},{%4,%5,%6,%7},{%8,%9},{%0,%1,%2,%3};"
        : "+f"(d[0]), "+f"(d[1]), "+f"(d[2]), "+f"(d[3])
        : "r"(a[0]), "r"(a[1]), "r"(a[2]), "r"(a[3]), "r"(b0), "r"(b1));
}
// 3-term split product: (Ab+As)(Bb+Bs) ~= Ab*Bb + Ab*Bs + As*Bb
__device__ __forceinline__ void mma3(float* d, const unsigned* ab, const unsigned* as, uint4 F) {
    mma_bf(d, ab, F.x, F.y);
    mma_bf(d, ab, F.z, F.w);
    mma_bf(d, as, F.x, F.y);
}
// load one 16x16 A tile's fragment for this thread from row-major [*, 64] matrix
__device__ __forceinline__ void load_asplit(const float* base, int nA, int nB, int k0,
                                            unsigned* ab, unsigned* as) {
    float2 v;
    v = *(const float2*)(base + (size_t)nA * 64 + k0);      split2(v, ab[0], as[0]);
    v = *(const float2*)(base + (size_t)nB * 64 + k0);      split2(v, ab[1], as[1]);
    v = *(const float2*)(base + (size_t)nA * 64 + k0 + 8);  split2(v, ab[2], as[2]);
    v = *(const float2*)(base + (size_t)nB * 64 + k0 + 8);  split2(v, ab[3], as[3]);
}

// ---------------- weight pre-split: W[C][64] -> fragment-ordered big/small bf16 ----------------
__global__ void k_presplit(const float* __restrict__ W, int off, int nfrag) {
    int f = blockIdx.x * blockDim.x + threadIdx.x;
    if (f >= nfrag) return;
    int lane = f & 31;
    int ks = (f >> 5) & 3;
    int j = f >> 7;
    int g = lane >> 2, t = lane & 3;
    const float* row = W + (size_t)(j * 8 + g) * 64;
    int k0 = ks * 16 + 2 * t;
    float w0 = row[k0], w1 = row[k0 + 1], w2 = row[k0 + 8], w3 = row[k0 + 9];
    unsigned b0 = pack_bf2(w0, w1);
    unsigned s0 = pack_bf2(w0 - bf_lo(b0), w1 - bf_hi(b0));
    unsigned b1 = pack_bf2(w2, w3);
    unsigned s1 = pack_bf2(w2 - bf_lo(b1), w3 - bf_hi(b1));
    g_wfrag[off + f] = make_uint4(b0, b1, s0, s1);
}

// ---------------- zero agg buffer + score ----------------
__global__ void k_zero() {
    int i = blockIdx.x * blockDim.x + threadIdx.x;
    const int tot4 = RR * NN * 16;
    if (i < tot4) ((float4*)g_agg)[i] = make_float4(0.f, 0.f, 0.f, 0.f);
    if (i < RR) g_score[i] = 0.f;
}

// ---------------- scatter: agg[r][dst] += feat[src], red.v4 ----------------
__global__ void k_scatter(const float* __restrict__ feat, int use_mix,
                          const int* __restrict__ ei) {
    unsigned idx = blockIdx.x * blockDim.x + threadIdx.x;
    if (idx >= (unsigned)RR * EE * 16u) return;
    const float* f = use_mix ? g_mix : feat;
    unsigned chunk = idx & 15u;
    unsigned e = idx >> 4;
    unsigned r = e / EE;
    unsigned eo = e - r * EE;
    int s = ei[(size_t)r * 2 * EE + eo];
    int d = ei[(size_t)r * 2 * EE + EE + eo];
    float4 v = *(const float4*)(f + (size_t)s * 64 + chunk * 4);
    float* o = g_agg + ((size_t)r * NN + d) * 64 + chunk * 4;
    asm volatile("red.global.add.v4.f32 [%0], {%1, %2, %3, %4};"
                 :: "l"(o), "f"(v.x), "f"(v.y), "f"(v.z), "f"(v.w) : "memory");
}

// ---------------- graphconv: g_h = relu(agg@Wrel.T + b + root@Wroot.T) ----------------
__global__ __launch_bounds__(256) void k_conv(
    const float* __restrict__ root_in, int use_mix, const float* __restrict__ brel) {
    const int r = blockIdx.y, tid = threadIdx.x;
    const int lane = tid & 31, warp = tid >> 5;
    const int g = lane >> 2, t = lane & 3;
    const int rowA = blockIdx.x * 128 + warp * 16 + g;
    const int rowB = rowA + 8;
    const int nA = min(rowA, NN - 1), nB = min(rowB, NN - 1);
    const float* Abase = g_agg + (size_t)r * NN * 64;
    const float* Rbase = use_mix ? g_mix : root_in;

    unsigned Ab[16], As[16], Rb[16], Rs[16];
#pragma unroll
    for (int ks = 0; ks < 4; ks++) {
        int k0 = ks * 16 + 2 * t;
        load_asplit(Abase, nA, nB, k0, Ab + ks * 4, As + ks * 4);
        load_asplit(Rbase, nA, nB, k0, Rb + ks * 4, Rs + ks * 4);
    }

    for (int j = 0; j < 8; j++) {
        float acc0[4] = {}, acc1[4] = {};
#pragma unroll
        for (int ks = 0; ks < 4; ks++) {
            uint4 Fr = __ldg(g_wfrag + WF_REL + ((((r * 8 + j) * 4 + ks) << 5) + lane));
            uint4 Fo = __ldg(g_wfrag + WF_ROOT + ((((r * 8 + j) * 4 + ks) << 5) + lane));
            mma3(acc0, Ab + ks * 4, As + ks * 4, Fr);
            mma3(acc1, Rb + ks * 4, Rs + ks * 4, Fo);
        }
        int c0 = j * 8 + 2 * t;
        float2 bb = *(const float2*)(brel + r * 64 + c0);
        if (rowA < NN) {
            float2 o;
            o.x = fmaxf(acc0[0] + acc1[0] + bb.x, 0.f);
            o.y = fmaxf(acc0[1] + acc1[1] + bb.y, 0.f);
            *(float2*)(g_h + ((size_t)r * NN + rowA) * 64 + c0) = o;
        }
        if (rowB < NN) {
            float2 o;
            o.x = fmaxf(acc0[2] + acc1[2] + bb.x, 0.f);
            o.y = fmaxf(acc0[3] + acc1[3] + bb.y, 0.f);
            *(float2*)(g_h + ((size_t)r * NN + rowB) * 64 + c0) = o;
        }
    }
}

// ---------------- GRU ----------------
__device__ __forceinline__ float gru_out(float gi_r, float gi_z, float gi_n,
                                         float gh_r, float gh_z, float gh_n, float p) {
    float rg = 1.f / (1.f + __expf(-(gi_r + gh_r)));
    float zg = 1.f / (1.f + __expf(-(gi_z + gh_z)));
    float ng = tanhf(gi_n + rg * gh_n);
    return (1.f - zg) * ng + zg * p;
}

__global__ __launch_bounds__(256) void k_gru(
    const float* __restrict__ past,
    const float* __restrict__ bi, const float* __restrict__ bh,
    float* __restrict__ cur) {
    const int r = blockIdx.y, tid = threadIdx.x;
    const int lane = tid & 31, warp = tid >> 5;
    const int g = lane >> 2, t = lane & 3;
    const int rowA = blockIdx.x * 128 + warp * 16 + g;
    const int rowB = rowA + 8;
    const int nA = min(rowA, NN - 1), nB = min(rowB, NN - 1);
    const float* Hbase = g_h + (size_t)r * NN * 64;
    const float* Pbase = past + (size_t)r * NN * 64;

    unsigned Hb[16], Hs[16], Pb[16], Ps[16];
#pragma unroll
    for (int ks = 0; ks < 4; ks++) {
        int k0 = ks * 16 + 2 * t;
        load_asplit(Hbase, nA, nB, k0, Hb + ks * 4, Hs + ks * 4);
        load_asplit(Pbase, nA, nB, k0, Pb + ks * 4, Ps + ks * 4);
    }

    for (int j = 0; j < 8; j++) {
        float acc[6][4] = {};
#pragma unroll
        for (int ks = 0; ks < 4; ks++) {
#pragma unroll
            for (int m = 0; m < 3; m++) {
                uint4 Fi = __ldg(g_wfrag + WF_WI + ((((m * 8 + j) * 4 + ks) << 5) + lane));
                uint4 Fh = __ldg(g_wfrag + WF_WH + ((((m * 8 + j) * 4 + ks) << 5) + lane));
                mma3(acc[m],     Hb + ks * 4, Hs + ks * 4, Fi);
                mma3(acc[3 + m], Pb + ks * 4, Ps + ks * 4, Fh);
            }
        }
        int c0 = j * 8 + 2 * t;
        float2 bir = *(const float2*)(bi + c0);
        float2 biz = *(const float2*)(bi + 64 + c0);
        float2 bin = *(const float2*)(bi + 128 + c0);
        float2 bhr = *(const float2*)(bh + c0);
        float2 bhz = *(const float2*)(bh + 64 + c0);
        float2 bhn = *(const float2*)(bh + 128 + c0);
        float2 pA = *(const float2*)(Pbase + (size_t)nA * 64 + c0);
        float2 pB = *(const float2*)(Pbase + (size_t)nB * 64 + c0);
        if (rowA < NN) {
            float2 o;
            o.x = gru_out(acc[0][0] + bir.x, acc[1][0] + biz.x, acc[2][0] + bin.x,
                          acc[3][0] + bhr.x, acc[4][0] + bhz.x, acc[5][0] + bhn.x, pA.x);
            o.y = gru_out(acc[0][1] + bir.y, acc[1][1] + biz.y, acc[2][1] + bin.y,
                          acc[3][1] + bhr.y, acc[4][1] + bhz.y, acc[5][1] + bhn.y, pA.y);
            *(float2*)(cur + ((size_t)r * NN + rowA) * 64 + c0) = o;
        }
        if (rowB < NN) {
            float2 o;
            o.x = gru_out(acc[0][2] + bir.x, acc[1][2] + biz.x, acc[2][2] + bin.x,
                          acc[3][2] + bhr.x, acc[4][2] + bhz.x, acc[5][2] + bhn.x, pB.x);
            o.y = gru_out(acc[0][3] + bir.y, acc[1][3] + biz.y, acc[2][3] + bin.y,
                          acc[3][3] + bhr.y, acc[4][3] + bhz.y, acc[5][3] + bhn.y, pB.y);
            *(float2*)(cur + ((size_t)r * NN + rowB) * 64 + c0) = o;
        }
    }
}

// ---------------- semantic attention: g_score[r] += sum q[c]*tanh((cur@kW.T+kb)[c]) ----------------
__global__ __launch_bounds__(256) void k_att(
    const float* __restrict__ cur, const float* __restrict__ kb,
    const float* __restrict__ q) {
    const int r = blockIdx.y, tid = threadIdx.x;
    const int lane = tid & 31, warp = tid >> 5;
    const int g = lane >> 2, t = lane & 3;
    const int rowA = blockIdx.x * 128 + warp * 16 + g;
    const int rowB = rowA + 8;
    const int nA = min(rowA, NN - 1), nB = min(rowB, NN - 1);
    const float* Cbase = cur + (size_t)r * NN * 64;

    unsigned Cb[16], Cs[16];
#pragma unroll
    for (int ks = 0; ks < 4; ks++)
        load_asplit(Cbase, nA, nB, ks * 16 + 2 * t, Cb + ks * 4, Cs + ks * 4);

    float ssum = 0.f;
    for (int j = 0; j < 8; j++) {
        float acc[4] = {};
#pragma unroll
        for (int ks = 0; ks < 4; ks++) {
            uint4 F = __ldg(g_wfrag + WF_ATT + (((j * 4 + ks) << 5) + lane));
            mma3(acc, Cb + ks * 4, Cs + ks * 4, F);
        }
        int c0 = j * 8 + 2 * t;
        float2 kbv = *(const float2*)(kb + c0);
        float2 qv  = *(const float2*)(q + c0);
        if (rowA < NN)
            ssum += qv.x * tanhf(acc[0] + kbv.x) + qv.y * tanhf(acc[1] + kbv.y);
        if (rowB < NN)
            ssum += qv.x * tanhf(acc[2] + kbv.x) + qv.y * tanhf(acc[3] + kbv.y);
    }
#pragma unroll
    for (int o = 16; o; o >>= 1) ssum += __shfl_down_sync(0xffffffffu, ssum, o);
    if (lane == 0) atomicAdd(&g_score[r], ssum);
}

// ---------------- softmax over relations ----------------
__global__ void k_softmax() {
    if (threadIdx.x == 0) {
        const float inv = 1.0f / (float)NN;
        float s0 = g_score[0] * inv, s1 = g_score[1] * inv, s2 = g_score[2] * inv;
        float m = fmaxf(s0, fmaxf(s1, s2));
        float e0 = __expf(s0 - m), e1 = __expf(s1 - m), e2 = __expf(s2 - m);
        float d = 1.f / (e0 + e1 + e2);
        g_attn[0] = e0 * d; g_attn[1] = e1 * d; g_attn[2] = e2 * d;
    }
}

// ---------------- attention mix ----------------
__global__ void k_mix(const float* __restrict__ cur) {
    int i = blockIdx.x * blockDim.x + threadIdx.x;
    if (i >= NN * 16) return;
    float a0 = g_attn[0], a1 = g_attn[1], a2 = g_attn[2];
    const float4* c = (const float4*)cur;
    float4 v0 = c[i], v1 = c[i + (size_t)NN * 16], v2 = c[i + (size_t)2 * NN * 16];
    float4 o;
    o.x = a0*v0.x + a1*v1.x + a2*v2.x;
    o.y = a0*v0.y + a1*v1.y + a2*v2.y;
    o.z = a0*v0.z + a1*v1.z + a2*v2.z;
    o.w = a0*v0.w + a1*v1.w + a2*v2.w;
    ((float4*)g_mix)[i] = o;
}

// ---------------- final projection ----------------
__global__ __launch_bounds__(128) void k_zfuse(
    const float* __restrict__ cur2, const float* __restrict__ postW,
    const float* __restrict__ postb) {
    int node = blockIdx.x * blockDim.x + threadIdx.x;
    if (node >= NN) return;
    float a0 = g_attn[0], a1 = g_attn[1], a2 = g_attn[2];
    const float4* c0 = (const float4*)(cur2 + (size_t)node * 64);
    const float4* c1 = (const float4*)(cur2 + ((size_t)NN + node) * 64);
    const float4* c2 = (const float4*)(cur2 + ((size_t)2 * NN + node) * 64);
    const float4* w0 = (const float4*)postW;
    const float4* w1 = (const float4*)(postW + 64);
    float z0 = postb[0], z1 = postb[1];
#pragma unroll
    for (int i = 0; i < 16; i++) {
        float4 u0 = c0[i], u1 = c1[i], u2 = c2[i];
        float4 m;
        m.x = a0*u0.x + a1*u1.x + a2*u2.x;
        m.y = a0*u0.y + a1*u1.y + a2*u2.y;
        m.z = a0*u0.z + a1*u1.z + a2*u2.z;
        m.w = a0*u0.w + a1*u1.w + a2*u2.w;
        float4 p0 = w0[i], p1 = w1[i];
        z0 += m.x*p0.x + m.y*p0.y + m.z*p0.z + m.w*p0.w;
        z1 += m.x*p1.x + m.y*p1.y + m.z*p1.z + m.w*p1.w;
    }
    g_z[2 * node]     = z0;
    g_z[2 * node + 1] = z1;
}

// ---------------- link scores ----------------
__global__ void k_score(const int* __restrict__ eli, const float* __restrict__ rel,
                        float* __restrict__ scores) {
    int idx = blockIdx.x * blockDim.x + threadIdx.x;
    if (idx >= RR * LL) return;
    int r = idx / LL;
    int l = idx - r * LL;
    int hd = eli[(size_t)r * 2 * LL + l];
    int tl = eli[(size_t)r * 2 * LL + LL + l];
    float hr = g_z[2 * hd], hi = g_z[2 * hd + 1];
    float tr = g_z[2 * tl], ti = g_z[2 * tl + 1];
    float rr = rel[2 * r], ri = rel[2 * r + 1];
    scores[idx] = hr * rr * tr + hi * rr * ti + hr * ri * ti - hi * ri * tr;
}

// ---------------- host ----------------
extern "C" void kernel_launch(void* const* d_in, const int* in_sizes, int n_in,
                              void* d_out, int out_size) {
    const float* x      = (const float*)d_in[0];
    const int*   ei     = (const int*)d_in[1];
    const int*   eli    = (const int*)d_in[2];
    const float* past1  = (const float*)d_in[3];
    const float* past2  = (const float*)d_in[4];
    const float* W1rel  = (const float*)d_in[5];
    const float* b1rel  = (const float*)d_in[6];
    const float* W1root = (const float*)d_in[7];
    const float* g1Wi   = (const float*)d_in[8];
    const float* g1Wh   = (const float*)d_in[9];
    const float* g1bi   = (const float*)d_in[10];
    const float* g1bh   = (const float*)d_in[11];
    const float* k1W    = (const float*)d_in[12];
    const float* k1b    = (const float*)d_in[13];
    const float* q1     = (const float*)d_in[14];
    const float* W2rel  = (const float*)d_in[15];
    const float* b2rel  = (const float*)d_in[16];
    const float* W2root = (const float*)d_in[17];
    const float* g2Wi   = (const float*)d_in[18];
    const float* g2Wh   = (const float*)d_in[19];
    const float* g2bi   = (const float*)d_in[20];
    const float* g2bh   = (const float*)d_in[21];
    const float* k2W    = (const float*)d_in[22];
    const float* k2b    = (const float*)d_in[23];
    const float* q2     = (const float*)d_in[24];
    const float* postW  = (const float*)d_in[25];
    const float* postb  = (const float*)d_in[26];
    const float* relemb = (const float*)d_in[27];

    float* out    = (float*)d_out;
    float* scores = out;
    float* cur1   = out + (size_t)RR * LL;
    float* cur2   = cur1 + (size_t)RR * NN * 64;

    dim3 gridL((NN + 127) / 128, RR);   // 782 x 3
    const int scat_blocks = (RR * EE * 16 + 255) / 256;

    // ---- layer 1 ----
    k_zero<<<18750, 256>>>();
    k_presplit<<<12, 256>>>(W1rel,  WF_REL,  3072);
    k_presplit<<<12, 256>>>(W1root, WF_ROOT, 3072);
    k_presplit<<<12, 256>>>(g1Wi,   WF_WI,   3072);
    k_presplit<<<12, 256>>>(g1Wh,   WF_WH,   3072);
    k_presplit<<<4, 256>>>(k1W,     WF_ATT,  1024);
    k_scatter<<<scat_blocks, 256>>>(x, 0, ei);
    k_conv<<<gridL, 256>>>(x, 0, b1rel);
    k_gru<<<gridL, 256>>>(past1, g1bi, g1bh, cur1);
    k_att<<<gridL, 256>>>(cur1, k1b, q1);
    k_softmax<<<1, 32>>>();
    k_mix<<<(NN * 16 + 255) / 256, 256>>>(cur1);

    // ---- layer 2 ----
    k_zero<<<18750, 256>>>();
    k_presplit<<<12, 256>>>(W2rel,  WF_REL,  3072);
    k_presplit<<<12, 256>>>(W2root, WF_ROOT, 3072);
    k_presplit<<<12, 256>>>(g2Wi,   WF_WI,   3072);
    k_presplit<<<12, 256>>>(g2Wh,   WF_WH,   3072);
    k_presplit<<<4, 256>>>(k2W,     WF_ATT,  1024);
    k_scatter<<<scat_blocks, 256>>>(x, 1, ei);
    k_conv<<<gridL, 256>>>(x, 1, b2rel);
    k_gru<<<gridL, 256>>>(past2, g2bi, g2bh, cur2);
    k_att<<<gridL, 256>>>(cur2, k2b, q2);
    k_softmax<<<1, 32>>>();

    // ---- head ----
    k_zfuse<<<(NN + 127) / 128, 128>>>(cur2, postW, postb);
    k_score<<<(RR * LL + 255) / 256, 256>>>(eli, relemb, scores);
}

// round 6
// speedup vs baseline: 4.7447x; 1.0551x over previous
#include <cuda_runtime.h>

#define NN 100000
#define RR 3
#define EE 800000
#define LL 200000

// ---------------- scratch ----------------
__device__ __align__(16) float g_agg[(size_t)2 * RR * NN * 64];  // both layers' segment sums
__device__ __align__(16) float g_mix[(size_t)NN * 64];
__device__ __align__(16) float g_z[(size_t)NN * 2];
__device__ float g_score[6];   // [layer*3 + r]

// pre-split weight fragments (bf16 big/small, MMA B-fragment order), both layers
#define WF_REL  0
#define WF_ROOT 3072
#define WF_WI   6144
#define WF_WH   9216
#define WF_ATT  12288
#define WF_LAYER 13312
__device__ __align__(16) uint4 g_wfrag[2 * WF_LAYER];

// ---------------- bf16 helpers ----------------
__device__ __forceinline__ unsigned pack_bf2(float lo, float hi) {
    unsigned d;
    asm("cvt.rn.bf16x2.f32 %0, %1, %2;" : "=r"(d) : "f"(hi), "f"(lo));
    return d;
}
__device__ __forceinline__ float bf_lo(unsigned v) { return __uint_as_float(v << 16); }
__device__ __forceinline__ float bf_hi(unsigned v) { return __uint_as_float(v & 0xffff0000u); }
__device__ __forceinline__ void split2(float x, float y, unsigned& big, unsigned& small) {
    big = pack_bf2(x, y);
    small = pack_bf2(x - bf_lo(big), y - bf_hi(big));
}
__device__ __forceinline__ void mma_bf(float* d, const unsigned* a, unsigned b0, unsigned b1) {
    asm volatile(
        "mma.sync.aligned.m16n8k16.row.col.f32.bf16.bf16.f32 "
        "{%0,%1,%2,%3},{%4,%5,%6,%7},{%8,%9},{%0,%1,%2,%3};"
        : "+f"(d[0]), "+f"(d[1]), "+f"(d[2]), "+f"(d[3])
        : "r"(a[0]), "r"(a[1]), "r"(a[2]), "r"(a[3]), "r"(b0), "r"(b1));
}
// 3-term split product: (Ab+As)(Bb+Bs) ~= Ab*Bb + Ab*Bs + As*Bb
__device__ __forceinline__ void mma3(float* d, const unsigned* ab, const unsigned* as, uint4 F) {
    mma_bf(d, ab, F.x, F.y);
    mma_bf(d, ab, F.z, F.w);
    mma_bf(d, as, F.x, F.y);
}
// load one 16x16 A tile's fragment from row-major [*, 64] matrix and split
__device__ __forceinline__ void load_asplit(const float* base, int nA, int nB, int k0,
                                            unsigned* ab, unsigned* as) {
    float2 v;
    v = *(const float2*)(base + (size_t)nA * 64 + k0);      split2(v.x, v.y, ab[0], as[0]);
    v = *(const float2*)(base + (size_t)nB * 64 + k0);      split2(v.x, v.y, ab[1], as[1]);
    v = *(const float2*)(base + (size_t)nA * 64 + k0 + 8);  split2(v.x, v.y, ab[2], as[2]);
    v = *(const float2*)(base + (size_t)nB * 64 + k0 + 8);  split2(v.x, v.y, ab[3], as[3]);
}

// ---------------- presplit ALL weights (both layers) in one launch ----------------
__global__ void k_presplit(
    const float* __restrict__ w1rel, const float* __restrict__ w1root,
    const float* __restrict__ wi1, const float* __restrict__ wh1,
    const float* __restrict__ kw1,
    const float* __restrict__ w2rel, const float* __restrict__ w2root,
    const float* __restrict__ wi2, const float* __restrict__ wh2,
    const float* __restrict__ kw2) {
    int f = blockIdx.x * blockDim.x + threadIdx.x;
    if (f >= 2 * WF_LAYER) return;
    int l = f / WF_LAYER;
    int fo = f - l * WF_LAYER;
    const float* W;
    int fl;
    if (fo < 3072)       { W = l ? w2rel : w1rel;   fl = fo; }
    else if (fo < 6144)  { W = l ? w2root : w1root; fl = fo - 3072; }
    else if (fo < 9216)  { W = l ? wi2 : wi1;       fl = fo - 6144; }
    else if (fo < 12288) { W = l ? wh2 : wh1;       fl = fo - 9216; }
    else                 { W = l ? kw2 : kw1;       fl = fo - 12288; }
    int lane = fl & 31;
    int ks = (fl >> 5) & 3;
    int j = fl >> 7;
    int g = lane >> 2, t = lane & 3;
    const float* row = W + (size_t)(j * 8 + g) * 64;
    int k0 = ks * 16 + 2 * t;
    float w0 = row[k0], w1 = row[k0 + 1], w2 = row[k0 + 8], w3 = row[k0 + 9];
    unsigned b0, s0, b1, s1;
    split2(w0, w1, b0, s0);
    split2(w2, w3, b1, s1);
    g_wfrag[f] = make_uint4(b0, b1, s0, s1);
}

// ---------------- zero both agg halves + scores ----------------
__global__ void k_zeroall() {
    int i = blockIdx.x * blockDim.x + threadIdx.x;
    const int tot4 = 2 * RR * NN * 16;
    if (i < tot4) ((float4*)g_agg)[i] = make_float4(0.f, 0.f, 0.f, 0.f);
    if (i < 6) g_score[i] = 0.f;
}

// ---------------- scatter: agg[layer][r][dst] += feat[src], red.v4 ----------------
__global__ void k_scatter(const float* __restrict__ feat, int layer,
                          const int* __restrict__ ei) {
    unsigned idx = blockIdx.x * blockDim.x + threadIdx.x;
    if (idx >= (unsigned)RR * EE * 16u) return;
    const float* f = layer ? g_mix : feat;
    unsigned chunk = idx & 15u;
    unsigned e = idx >> 4;
    unsigned r = e / EE;
    unsigned eo = e - r * EE;
    int s = ei[(size_t)r * 2 * EE + eo];
    int d = ei[(size_t)r * 2 * EE + EE + eo];
    float4 v = *(const float4*)(f + (size_t)s * 64 + chunk * 4);
    float* o = g_agg + ((size_t)layer * RR + r) * NN * 64 + (size_t)d * 64 + chunk * 4;
    asm volatile("red.global.add.v4.f32 [%0], {%1, %2, %3, %4};"
                 :: "l"(o), "f"(v.x), "f"(v.y), "f"(v.z), "f"(v.w) : "memory");
}

// ---------------- GRU epilogue ----------------
__device__ __forceinline__ float gru_out(float gi_r, float gi_z, float gi_n,
                                         float gh_r, float gh_z, float gh_n, float p) {
    float rg = 1.f / (1.f + __expf(-(gi_r + gh_r)));
    float zg = 1.f / (1.f + __expf(-(gi_z + gh_z)));
    float ng = tanhf(gi_n + rg * gh_n);
    return (1.f - zg) * ng + zg * p;
}

// ---------------- fused layer: conv -> GRU -> attention score ----------------
__global__ __launch_bounds__(256) void k_layer(
    const float* __restrict__ root_in, int layer,
    const float* __restrict__ past,
    const float* __restrict__ brel,
    const float* __restrict__ bi, const float* __restrict__ bh,
    const float* __restrict__ kb, const float* __restrict__ q,
    float* __restrict__ cur) {
    const int r = blockIdx.y, tid = threadIdx.x;
    const int lane = tid & 31, warp = tid >> 5;
    const int g = lane >> 2, t = lane & 3;
    const int rowA = blockIdx.x * 128 + warp * 16 + g;
    const int rowB = rowA + 8;
    const int nA = min(rowA, NN - 1), nB = min(rowB, NN - 1);
    const int WB = layer * WF_LAYER;
    const float* Abase = g_agg + ((size_t)layer * RR + r) * NN * 64;
    const float* Rbase = layer ? g_mix : root_in;
    const float* Pbase = past + (size_t)r * NN * 64;

    // ===== phase A: graphconv, build H fragments in registers =====
    unsigned Hb[16], Hs[16];
    {
        unsigned Ab[16], As[16], Rb[16], Rs[16];
#pragma unroll
        for (int ks = 0; ks < 4; ks++) {
            int k0 = ks * 16 + 2 * t;
            load_asplit(Abase, nA, nB, k0, Ab + ks * 4, As + ks * 4);
            load_asplit(Rbase, nA, nB, k0, Rb + ks * 4, Rs + ks * 4);
        }
#pragma unroll
        for (int j = 0; j < 8; j++) {
            float acc0[4] = {}, acc1[4] = {};
#pragma unroll
            for (int ks = 0; ks < 4; ks++) {
                uint4 Fr = __ldg(g_wfrag + WB + WF_REL + ((((r * 8 + j) * 4 + ks) << 5) + lane));
                uint4 Fo = __ldg(g_wfrag + WB + WF_ROOT + ((((r * 8 + j) * 4 + ks) << 5) + lane));
                mma3(acc0, Ab + ks * 4, As + ks * 4, Fr);
                mma3(acc1, Rb + ks * 4, Rs + ks * 4, Fo);
            }
            int c0 = j * 8 + 2 * t;
            float2 bb = *(const float2*)(brel + r * 64 + c0);
            float h0 = fmaxf(acc0[0] + acc1[0] + bb.x, 0.f);
            float h1 = fmaxf(acc0[1] + acc1[1] + bb.y, 0.f);
            float h2 = fmaxf(acc0[2] + acc1[2] + bb.x, 0.f);
            float h3 = fmaxf(acc0[3] + acc1[3] + bb.y, 0.f);
            // C-fragment -> A-fragment in-register repack
            int slot = (j >> 1) * 4 + ((j & 1) ? 2 : 0);
            split2(h0, h1, Hb[slot], Hs[slot]);
            split2(h2, h3, Hb[slot + 1], Hs[slot + 1]);
        }
    }

    // ===== phase B: GRU, build C fragments in registers =====
    unsigned Cb[16], Cs[16];
    {
        unsigned Pb[16], Ps[16];
#pragma unroll
        for (int ks = 0; ks < 4; ks++)
            load_asplit(Pbase, nA, nB, ks * 16 + 2 * t, Pb + ks * 4, Ps + ks * 4);
#pragma unroll
        for (int j = 0; j < 8; j++) {
            float acc[6][4] = {};
#pragma unroll
            for (int ks = 0; ks < 4; ks++) {
#pragma unroll
                for (int m = 0; m < 3; m++) {
                    uint4 Fi = __ldg(g_wfrag + WB + WF_WI + ((((m * 8 + j) * 4 + ks) << 5) + lane));
                    uint4 Fh = __ldg(g_wfrag + WB + WF_WH + ((((m * 8 + j) * 4 + ks) << 5) + lane));
                    mma3(acc[m],     Hb + ks * 4, Hs + ks * 4, Fi);
                    mma3(acc[3 + m], Pb + ks * 4, Ps + ks * 4, Fh);
                }
            }
            int c0 = j * 8 + 2 * t;
            float2 bir = *(const float2*)(bi + c0);
            float2 biz = *(const float2*)(bi + 64 + c0);
            float2 bin = *(const float2*)(bi + 128 + c0);
            float2 bhr = *(const float2*)(bh + c0);
            float2 bhz = *(const float2*)(bh + 64 + c0);
            float2 bhn = *(const float2*)(bh + 128 + c0);
            float2 pA = *(const float2*)(Pbase + (size_t)nA * 64 + c0);
            float2 pB = *(const float2*)(Pbase + (size_t)nB * 64 + c0);
            float o0 = gru_out(acc[0][0] + bir.x, acc[1][0] + biz.x, acc[2][0] + bin.x,
                               acc[3][0] + bhr.x, acc[4][0] + bhz.x, acc[5][0] + bhn.x, pA.x);
            float o1 = gru_out(acc[0][1] + bir.y, acc[1][1] + biz.y, acc[2][1] + bin.y,
                               acc[3][1] + bhr.y, acc[4][1] + bhz.y, acc[5][1] + bhn.y, pA.y);
            float o2 = gru_out(acc[0][2] + bir.x, acc[1][2] + biz.x, acc[2][2] + bin.x,
                               acc[3][2] + bhr.x, acc[4][2] + bhz.x, acc[5][2] + bhn.x, pB.x);
            float o3 = gru_out(acc[0][3] + bir.y, acc[1][3] + biz.y, acc[2][3] + bin.y,
                               acc[3][3] + bhr.y, acc[4][3] + bhz.y, acc[5][3] + bhn.y, pB.y);
            if (rowA < NN) *(float2*)(cur + ((size_t)r * NN + rowA) * 64 + c0) = make_float2(o0, o1);
            if (rowB < NN) *(float2*)(cur + ((size_t)r * NN + rowB) * 64 + c0) = make_float2(o2, o3);
            int slot = (j >> 1) * 4 + ((j & 1) ? 2 : 0);
            split2(o0, o1, Cb[slot], Cs[slot]);
            split2(o2, o3, Cb[slot + 1], Cs[slot + 1]);
        }
    }

    // ===== phase C: attention score =====
    float ssum = 0.f;
#pragma unroll
    for (int j = 0; j < 8; j++) {
        float acc[4] = {};
#pragma unroll
        for (int ks = 0; ks < 4; ks++) {
            uint4 F = __ldg(g_wfrag + WB + WF_ATT + (((j * 4 + ks) << 5) + lane));
            mma3(acc, Cb + ks * 4, Cs + ks * 4, F);
        }
        int c0 = j * 8 + 2 * t;
        float2 kbv = *(const float2*)(kb + c0);
        float2 qv  = *(const float2*)(q + c0);
        if (rowA < NN)
            ssum += qv.x * tanhf(acc[0] + kbv.x) + qv.y * tanhf(acc[1] + kbv.y);
        if (rowB < NN)
            ssum += qv.x * tanhf(acc[2] + kbv.x) + qv.y * tanhf(acc[3] + kbv.y);
    }
#pragma unroll
    for (int o = 16; o; o >>= 1) ssum += __shfl_down_sync(0xffffffffu, ssum, o);
    if (lane == 0) atomicAdd(&g_score[layer * 3 + r], ssum);
}

// ---------------- softmax helper (inline, per thread) ----------------
__device__ __forceinline__ void softmax3(int layer, float& a0, float& a1, float& a2) {
    const float inv = 1.0f / (float)NN;
    float s0 = g_score[layer * 3 + 0] * inv;
    float s1 = g_score[layer * 3 + 1] * inv;
    float s2 = g_score[layer * 3 + 2] * inv;
    float m = fmaxf(s0, fmaxf(s1, s2));
    float e0 = __expf(s0 - m), e1 = __expf(s1 - m), e2 = __expf(s2 - m);
    float d = 1.f / (e0 + e1 + e2);
    a0 = e0 * d; a1 = e1 * d; a2 = e2 * d;
}

// ---------------- attention mix (softmax fused) ----------------
__global__ void k_mix(const float* __restrict__ cur) {
    int i = blockIdx.x * blockDim.x + threadIdx.x;
    if (i >= NN * 16) return;
    float a0, a1, a2;
    softmax3(0, a0, a1, a2);
    const float4* c = (const float4*)cur;
    float4 v0 = c[i], v1 = c[i + (size_t)NN * 16], v2 = c[i + (size_t)2 * NN * 16];
    float4 o;
    o.x = a0*v0.x + a1*v1.x + a2*v2.x;
    o.y = a0*v0.y + a1*v1.y + a2*v2.y;
    o.z = a0*v0.z + a1*v1.z + a2*v2.z;
    o.w = a0*v0.w + a1*v1.w + a2*v2.w;
    ((float4*)g_mix)[i] = o;
}

// ---------------- final projection (softmax fused) ----------------
__global__ __launch_bounds__(128) void k_zfuse(
    const float* __restrict__ cur2, const float* __restrict__ postW,
    const float* __restrict__ postb) {
    int node = blockIdx.x * blockDim.x + threadIdx.x;
    if (node >= NN) return;
    float a0, a1, a2;
    softmax3(1, a0, a1, a2);
    const float4* c0 = (const float4*)(cur2 + (size_t)node * 64);
    const float4* c1 = (const float4*)(cur2 + ((size_t)NN + node) * 64);
    const float4* c2 = (const float4*)(cur2 + ((size_t)2 * NN + node) * 64);
    const float4* w0 = (const float4*)postW;
    const float4* w1 = (const float4*)(postW + 64);
    float z0 = postb[0], z1 = postb[1];
#pragma unroll
    for (int i = 0; i < 16; i++) {
        float4 u0 = c0[i], u1 = c1[i], u2 = c2[i];
        float4 m;
        m.x = a0*u0.x + a1*u1.x + a2*u2.x;
        m.y = a0*u0.y + a1*u1.y + a2*u2.y;
        m.z = a0*u0.z + a1*u1.z + a2*u2.z;
        m.w = a0*u0.w + a1*u1.w + a2*u2.w;
        float4 p0 = w0[i], p1 = w1[i];
        z0 += m.x*p0.x + m.y*p0.y + m.z*p0.z + m.w*p0.w;
        z1 += m.x*p1.x + m.y*p1.y + m.z*p1.z + m.w*p1.w;
    }
    g_z[2 * node]     = z0;
    g_z[2 * node + 1] = z1;
}

// ---------------- link scores ----------------
__global__ void k_score(const int* __restrict__ eli, const float* __restrict__ rel,
                        float* __restrict__ scores) {
    int idx = blockIdx.x * blockDim.x + threadIdx.x;
    if (idx >= RR * LL) return;
    int r = idx / LL;
    int l = idx - r * LL;
    int hd = eli[(size_t)r * 2 * LL + l];
    int tl = eli[(size_t)r * 2 * LL + LL + l];
    float hr = g_z[2 * hd], hi = g_z[2 * hd + 1];
    float tr = g_z[2 * tl], ti = g_z[2 * tl + 1];
    float rr = rel[2 * r], ri = rel[2 * r + 1];
    scores[idx] = hr * rr * tr + hi * rr * ti + hr * ri * ti - hi * ri * tr;
}

// ---------------- host ----------------
extern "C" void kernel_launch(void* const* d_in, const int* in_sizes, int n_in,
                              void* d_out, int out_size) {
    const float* x      = (const float*)d_in[0];
    const int*   ei     = (const int*)d_in[1];
    const int*   eli    = (const int*)d_in[2];
    const float* past1  = (const float*)d_in[3];
    const float* past2  = (const float*)d_in[4];
    const float* W1rel  = (const float*)d_in[5];
    const float* b1rel  = (const float*)d_in[6];
    const float* W1root = (const float*)d_in[7];
    const float* g1Wi   = (const float*)d_in[8];
    const float* g1Wh   = (const float*)d_in[9];
    const float* g1bi   = (const float*)d_in[10];
    const float* g1bh   = (const float*)d_in[11];
    const float* k1W    = (const float*)d_in[12];
    const float* k1b    = (const float*)d_in[13];
    const float* q1     = (const float*)d_in[14];
    const float* W2rel  = (const float*)d_in[15];
    const float* b2rel  = (const float*)d_in[16];
    const float* W2root = (const float*)d_in[17];
    const float* g2Wi   = (const float*)d_in[18];
    const float* g2Wh   = (const float*)d_in[19];
    const float* g2bi   = (const float*)d_in[20];
    const float* g2bh   = (const float*)d_in[21];
    const float* k2W    = (const float*)d_in[22];
    const float* k2b    = (const float*)d_in[23];
    const float* q2     = (const float*)d_in[24];
    const float* postW  = (const float*)d_in[25];
    const float* postb  = (const float*)d_in[26];
    const float* relemb = (const float*)d_in[27];

    float* out    = (float*)d_out;
    float* scores = out;
    float* cur1   = out + (size_t)RR * LL;
    float* cur2   = cur1 + (size_t)RR * NN * 64;

    dim3 gridL((NN + 127) / 128, RR);   // 782 x 3
    const int scat_blocks = (RR * EE * 16 + 255) / 256;

    // 1: zero both agg halves + scores
    k_zeroall<<<(2 * RR * NN * 16 + 255) / 256, 256>>>();
    // 2: presplit all weights (both layers) in one launch
    k_presplit<<<(2 * WF_LAYER + 255) / 256, 256>>>(
        W1rel, W1root, g1Wi, g1Wh, k1W, W2rel, W2root, g2Wi, g2Wh, k2W);
    // 3: layer-1 scatter
    k_scatter<<<scat_blocks, 256>>>(x, 0, ei);
    // 4: fused layer 1 (conv+gru+att)
    k_layer<<<gridL, 256>>>(x, 0, past1, b1rel, g1bi, g1bh, k1b, q1, cur1);
    // 5: softmax+mix
    k_mix<<<(NN * 16 + 255) / 256, 256>>>(cur1);
    // 6: layer-2 scatter  (profiled launch under -s 5 -c 1)
    k_scatter<<<scat_blocks, 256>>>(x, 1, ei);
    // 7: fused layer 2
    k_layer<<<gridL, 256>>>(x, 1, past2, b2rel, g2bi, g2bh, k2b, q2, cur2);
    // 8: softmax+projection
    k_zfuse<<<(NN + 127) / 128, 128>>>(cur2, postW, postb);
    // 9: link scores
    k_score<<<(RR * LL + 255) / 256, 256>>>(eli, relemb, scores);
}

// round 7
// speedup vs baseline: 4.8626x; 1.0248x over previous
#include <cuda_runtime.h>

#define NN 100000
#define RR 3
#define EE 800000
#define LL 200000
#define SPAD 68  // SMEM stage row stride (floats): conflict-free for (g,t) fragment access

// ---------------- scratch ----------------
__device__ __align__(16) float g_agg[(size_t)2 * RR * NN * 64];  // both layers' segment sums
__device__ __align__(16) float g_mix[(size_t)NN * 64];
__device__ __align__(16) float g_z[(size_t)NN * 2];
__device__ float g_score[6];   // [layer*3 + r]

// pre-split weight fragments (bf16 big/small, MMA B-fragment order), both layers
#define WF_REL  0
#define WF_ROOT 3072
#define WF_WI   6144
#define WF_WH   9216
#define WF_ATT  12288
#define WF_LAYER 13312
__device__ __align__(16) uint4 g_wfrag[2 * WF_LAYER];

// ---------------- bf16 helpers ----------------
__device__ __forceinline__ unsigned pack_bf2(float lo, float hi) {
    unsigned d;
    asm("cvt.rn.bf16x2.f32 %0, %1, %2;" : "=r"(d) : "f"(hi), "f"(lo));
    return d;
}
__device__ __forceinline__ float bf_lo(unsigned v) { return __uint_as_float(v << 16); }
__device__ __forceinline__ float bf_hi(unsigned v) { return __uint_as_float(v & 0xffff0000u); }
__device__ __forceinline__ void split2(float x, float y, unsigned& big, unsigned& small) {
    big = pack_bf2(x, y);
    small = pack_bf2(x - bf_lo(big), y - bf_hi(big));
}
__device__ __forceinline__ void mma_bf(float* d, const unsigned* a, unsigned b0, unsigned b1) {
    asm volatile(
        "mma.sync.aligned.m16n8k16.row.col.f32.bf16.bf16.f32 "
        "{%0,%1,%2,%3},{%4,%5,%6,%7},{%8,%9},{%0,%1,%2,%3};"
        : "+f"(d[0]), "+f"(d[1]), "+f"(d[2]), "+f"(d[3])
        : "r"(a[0]), "r"(a[1]), "r"(a[2]), "r"(a[3]), "r"(b0), "r"(b1));
}
// 3-term split product: (Ab+As)(Bb+Bs) ~= Ab*Bb + Ab*Bs + As*Bb
__device__ __forceinline__ void mma3(float* d, const unsigned* ab, const unsigned* as, uint4 F) {
    mma_bf(d, ab, F.x, F.y);
    mma_bf(d, ab, F.z, F.w);
    mma_bf(d, as, F.x, F.y);
}
// load one 16x16 A-tile fragment from row-major [*, 64] global matrix and split
__device__ __forceinline__ void load_asplit(const float* base, int nA, int nB, int k0,
                                            unsigned* ab, unsigned* as) {
    float2 v;
    v = *(const float2*)(base + (size_t)nA * 64 + k0);      split2(v.x, v.y, ab[0], as[0]);
    v = *(const float2*)(base + (size_t)nB * 64 + k0);      split2(v.x, v.y, ab[1], as[1]);
    v = *(const float2*)(base + (size_t)nA * 64 + k0 + 8);  split2(v.x, v.y, ab[2], as[2]);
    v = *(const float2*)(base + (size_t)nB * 64 + k0 + 8);  split2(v.x, v.y, ab[3], as[3]);
}
// same but from the per-warp SMEM stage (16 rows, stride SPAD); local rows g / g+8
__device__ __forceinline__ void load_asplit_s(const float* stage, int g, int k0,
                                              unsigned* ab, unsigned* as) {
    float2 v;
    v = *(const float2*)(stage + g * SPAD + k0);            split2(v.x, v.y, ab[0], as[0]);
    v = *(const float2*)(stage + (g + 8) * SPAD + k0);      split2(v.x, v.y, ab[1], as[1]);
    v = *(const float2*)(stage + g * SPAD + k0 + 8);        split2(v.x, v.y, ab[2], as[2]);
    v = *(const float2*)(stage + (g + 8) * SPAD + k0 + 8);  split2(v.x, v.y, ab[3], as[3]);
}

// ---------------- presplit ALL weights (both layers) in one launch ----------------
__global__ void k_presplit(
    const float* __restrict__ w1rel, const float* __restrict__ w1root,
    const float* __restrict__ wi1, const float* __restrict__ wh1,
    const float* __restrict__ kw1,
    const float* __restrict__ w2rel, const float* __restrict__ w2root,
    const float* __restrict__ wi2, const float* __restrict__ wh2,
    const float* __restrict__ kw2) {
    int f = blockIdx.x * blockDim.x + threadIdx.x;
    if (f >= 2 * WF_LAYER) return;
    int l = f / WF_LAYER;
    int fo = f - l * WF_LAYER;
    const float* W;
    int fl;
    if (fo < 3072)       { W = l ? w2rel : w1rel;   fl = fo; }
    else if (fo < 6144)  { W = l ? w2root : w1root; fl = fo - 3072; }
    else if (fo < 9216)  { W = l ? wi2 : wi1;       fl = fo - 6144; }
    else if (fo < 12288) { W = l ? wh2 : wh1;       fl = fo - 9216; }
    else                 { W = l ? kw2 : kw1;       fl = fo - 12288; }
    int lane = fl & 31;
    int ks = (fl >> 5) & 3;
    int j = fl >> 7;
    int g = lane >> 2, t = lane & 3;
    const float* row = W + (size_t)(j * 8 + g) * 64;
    int k0 = ks * 16 + 2 * t;
    float w0 = row[k0], w1 = row[k0 + 1], w2 = row[k0 + 8], w3 = row[k0 + 9];
    unsigned b0, s0, b1, s1;
    split2(w0, w1, b0, s0);
    split2(w2, w3, b1, s1);
    g_wfrag[f] = make_uint4(b0, b1, s0, s1);
}

// ---------------- zero both agg halves + scores ----------------
__global__ void k_zeroall() {
    int i = blockIdx.x * blockDim.x + threadIdx.x;
    const int tot4 = 2 * RR * NN * 16;
    if (i < tot4) ((float4*)g_agg)[i] = make_float4(0.f, 0.f, 0.f, 0.f);
    if (i < 6) g_score[i] = 0.f;
}

// ---------------- scatter: agg[layer][r][dst] += feat[src], red.v4 ----------------
__global__ void k_scatter(const float* __restrict__ feat, int layer,
                          const int* __restrict__ ei) {
    unsigned idx = blockIdx.x * blockDim.x + threadIdx.x;
    if (idx >= (unsigned)RR * EE * 16u) return;
    const float* f = layer ? g_mix : feat;
    unsigned chunk = idx & 15u;
    unsigned e = idx >> 4;
    unsigned r = e / EE;
    unsigned eo = e - r * EE;
    int s = ei[(size_t)r * 2 * EE + eo];
    int d = ei[(size_t)r * 2 * EE + EE + eo];
    float4 v = *(const float4*)(f + (size_t)s * 64 + chunk * 4);
    float* o = g_agg + ((size_t)layer * RR + r) * NN * 64 + (size_t)d * 64 + chunk * 4;
    asm volatile("red.global.add.v4.f32 [%0], {%1, %2, %3, %4};"
                 :: "l"(o), "f"(v.x), "f"(v.y), "f"(v.z), "f"(v.w) : "memory");
}

// ---------------- GRU epilogue ----------------
__device__ __forceinline__ float gru_out(float gi_r, float gi_z, float gi_n,
                                         float gh_r, float gh_z, float gh_n, float p) {
    float rg = 1.f / (1.f + __expf(-(gi_r + gh_r)));
    float zg = 1.f / (1.f + __expf(-(gi_z + gh_z)));
    float ng = tanhf(gi_n + rg * gh_n);
    return (1.f - zg) * ng + zg * p;
}

// ---------------- fused layer: conv -> GRU -> attention score ----------------
__global__ __launch_bounds__(256, 2) void k_layer(
    const float* __restrict__ root_in, int layer,
    const float* __restrict__ past,
    const float* __restrict__ brel,
    const float* __restrict__ bi, const float* __restrict__ bh,
    const float* __restrict__ kb, const float* __restrict__ q,
    float* __restrict__ cur) {
    __shared__ float sStage[8 * 16 * SPAD];   // 34816 B: per-warp 16x64 stage (stride SPAD)
    const int r = blockIdx.y, tid = threadIdx.x;
    const int lane = tid & 31, warp = tid >> 5;
    const int g = lane >> 2, t = lane & 3;
    const int rowA = blockIdx.x * 128 + warp * 16 + g;
    const int rowB = rowA + 8;
    const int nA = min(rowA, NN - 1), nB = min(rowB, NN - 1);
    const int WB = layer * WF_LAYER;
    const float* Abase = g_agg + ((size_t)layer * RR + r) * NN * 64;
    const float* Rbase = layer ? g_mix : root_in;
    const float* Pbase = past + (size_t)r * NN * 64;
    float* stage = sStage + warp * 16 * SPAD;

    // ===== phase A: graphconv -> H into SMEM stage =====
    {
        unsigned Ab[16], As[16], Rb[16], Rs[16];
#pragma unroll
        for (int ks = 0; ks < 4; ks++) {
            int k0 = ks * 16 + 2 * t;
            load_asplit(Abase, nA, nB, k0, Ab + ks * 4, As + ks * 4);
            load_asplit(Rbase, nA, nB, k0, Rb + ks * 4, Rs + ks * 4);
        }
#pragma unroll
        for (int j = 0; j < 8; j++) {
            float acc0[4] = {}, acc1[4] = {};
#pragma unroll
            for (int ks = 0; ks < 4; ks++) {
                uint4 Fr = __ldg(g_wfrag + WB + WF_REL + ((((r * 8 + j) * 4 + ks) << 5) + lane));
                uint4 Fo = __ldg(g_wfrag + WB + WF_ROOT + ((((r * 8 + j) * 4 + ks) << 5) + lane));
                mma3(acc0, Ab + ks * 4, As + ks * 4, Fr);
                mma3(acc1, Rb + ks * 4, Rs + ks * 4, Fo);
            }
            int c0 = j * 8 + 2 * t;
            float2 bb = *(const float2*)(brel + r * 64 + c0);
            *(float2*)(stage + g * SPAD + c0) =
                make_float2(fmaxf(acc0[0] + acc1[0] + bb.x, 0.f),
                            fmaxf(acc0[1] + acc1[1] + bb.y, 0.f));
            *(float2*)(stage + (g + 8) * SPAD + c0) =
                make_float2(fmaxf(acc0[2] + acc1[2] + bb.x, 0.f),
                            fmaxf(acc0[3] + acc1[3] + bb.y, 0.f));
        }
    }
    __syncwarp();

    // ===== phase B: GRU; H from stage, C -> stage =====
    {
        unsigned Hb[16], Hs[16], Pb[16], Ps[16];
#pragma unroll
        for (int ks = 0; ks < 4; ks++) {
            int k0 = ks * 16 + 2 * t;
            load_asplit_s(stage, g, k0, Hb + ks * 4, Hs + ks * 4);
            load_asplit(Pbase, nA, nB, k0, Pb + ks * 4, Ps + ks * 4);
        }
        __syncwarp();   // all lanes consumed H before overwriting stage with C
#pragma unroll
        for (int j = 0; j < 8; j++) {
            float acc[6][4] = {};
#pragma unroll
            for (int ks = 0; ks < 4; ks++) {
#pragma unroll
                for (int m = 0; m < 3; m++) {
                    uint4 Fi = __ldg(g_wfrag + WB + WF_WI + ((((m * 8 + j) * 4 + ks) << 5) + lane));
                    uint4 Fh = __ldg(g_wfrag + WB + WF_WH + ((((m * 8 + j) * 4 + ks) << 5) + lane));
                    mma3(acc[m],     Hb + ks * 4, Hs + ks * 4, Fi);
                    mma3(acc[3 + m], Pb + ks * 4, Ps + ks * 4, Fh);
                }
            }
            int c0 = j * 8 + 2 * t;
            float2 bir = *(const float2*)(bi + c0);
            float2 biz = *(const float2*)(bi + 64 + c0);
            float2 bin = *(const float2*)(bi + 128 + c0);
            float2 bhr = *(const float2*)(bh + c0);
            float2 bhz = *(const float2*)(bh + 64 + c0);
            float2 bhn = *(const float2*)(bh + 128 + c0);
            float2 pA = *(const float2*)(Pbase + (size_t)nA * 64 + c0);
            float2 pB = *(const float2*)(Pbase + (size_t)nB * 64 + c0);
            float o0 = gru_out(acc[0][0] + bir.x, acc[1][0] + biz.x, acc[2][0] + bin.x,
                               acc[3][0] + bhr.x, acc[4][0] + bhz.x, acc[5][0] + bhn.x, pA.x);
            float o1 = gru_out(acc[0][1] + bir.y, acc[1][1] + biz.y, acc[2][1] + bin.y,
                               acc[3][1] + bhr.y, acc[4][1] + bhz.y, acc[5][1] + bhn.y, pA.y);
            float o2 = gru_out(acc[0][2] + bir.x, acc[1][2] + biz.x, acc[2][2] + bin.x,
                               acc[3][2] + bhr.x, acc[4][2] + bhz.x, acc[5][2] + bhn.x, pB.x);
            float o3 = gru_out(acc[0][3] + bir.y, acc[1][3] + biz.y, acc[2][3] + bin.y,
                               acc[3][3] + bhr.y, acc[4][3] + bhz.y, acc[5][3] + bhn.y, pB.y);
            if (rowA < NN) *(float2*)(cur + ((size_t)r * NN + rowA) * 64 + c0) = make_float2(o0, o1);
            if (rowB < NN) *(float2*)(cur + ((size_t)r * NN + rowB) * 64 + c0) = make_float2(o2, o3);
            *(float2*)(stage + g * SPAD + c0) = make_float2(o0, o1);
            *(float2*)(stage + (g + 8) * SPAD + c0) = make_float2(o2, o3);
        }
    }
    __syncwarp();

    // ===== phase C: attention score; C from stage =====
    {
        unsigned Cb[16], Cs[16];
#pragma unroll
        for (int ks = 0; ks < 4; ks++)
            load_asplit_s(stage, g, ks * 16 + 2 * t, Cb + ks * 4, Cs + ks * 4);

        float ssum = 0.f;
#pragma unroll
        for (int j = 0; j < 8; j++) {
            float acc[4] = {};
#pragma unroll
            for (int ks = 0; ks < 4; ks++) {
                uint4 F = __ldg(g_wfrag + WB + WF_ATT + (((j * 4 + ks) << 5) + lane));
                mma3(acc, Cb + ks * 4, Cs + ks * 4, F);
            }
            int c0 = j * 8 + 2 * t;
            float2 kbv = *(const float2*)(kb + c0);
            float2 qv  = *(const float2*)(q + c0);
            if (rowA < NN)
                ssum += qv.x * tanhf(acc[0] + kbv.x) + qv.y * tanhf(acc[1] + kbv.y);
            if (rowB < NN)
                ssum += qv.x * tanhf(acc[2] + kbv.x) + qv.y * tanhf(acc[3] + kbv.y);
        }
#pragma unroll
        for (int o = 16; o; o >>= 1) ssum += __shfl_down_sync(0xffffffffu, ssum, o);
        if (lane == 0) atomicAdd(&g_score[layer * 3 + r], ssum);
    }
}

// ---------------- softmax helper (inline, per thread) ----------------
__device__ __forceinline__ void softmax3(int layer, float& a0, float& a1, float& a2) {
    const float inv = 1.0f / (float)NN;
    float s0 = g_score[layer * 3 + 0] * inv;
    float s1 = g_score[layer * 3 + 1] * inv;
    float s2 = g_score[layer * 3 + 2] * inv;
    float m = fmaxf(s0, fmaxf(s1, s2));
    float e0 = __expf(s0 - m), e1 = __expf(s1 - m), e2 = __expf(s2 - m);
    float d = 1.f / (e0 + e1 + e2);
    a0 = e0 * d; a1 = e1 * d; a2 = e2 * d;
}

// ---------------- attention mix (softmax fused) ----------------
__global__ void k_mix(const float* __restrict__ cur) {
    int i = blockIdx.x * blockDim.x + threadIdx.x;
    if (i >= NN * 16) return;
    float a0, a1, a2;
    softmax3(0, a0, a1, a2);
    const float4* c = (const float4*)cur;
    float4 v0 = c[i], v1 = c[i + (size_t)NN * 16], v2 = c[i + (size_t)2 * NN * 16];
    float4 o;
    o.x = a0*v0.x + a1*v1.x + a2*v2.x;
    o.y = a0*v0.y + a1*v1.y + a2*v2.y;
    o.z = a0*v0.z + a1*v1.z + a2*v2.z;
    o.w = a0*v0.w + a1*v1.w + a2*v2.w;
    ((float4*)g_mix)[i] = o;
}

// ---------------- final projection (softmax fused) ----------------
__global__ __launch_bounds__(128) void k_zfuse(
    const float* __restrict__ cur2, const float* __restrict__ postW,
    const float* __restrict__ postb) {
    int node = blockIdx.x * blockDim.x + threadIdx.x;
    if (node >= NN) return;
    float a0, a1, a2;
    softmax3(1, a0, a1, a2);
    const float4* c0 = (const float4*)(cur2 + (size_t)node * 64);
    const float4* c1 = (const float4*)(cur2 + ((size_t)NN + node) * 64);
    const float4* c2 = (const float4*)(cur2 + ((size_t)2 * NN + node) * 64);
    const float4* w0 = (const float4*)postW;
    const float4* w1 = (const float4*)(postW + 64);
    float z0 = postb[0], z1 = postb[1];
#pragma unroll
    for (int i = 0; i < 16; i++) {
        float4 u0 = c0[i], u1 = c1[i], u2 = c2[i];
        float4 m;
        m.x = a0*u0.x + a1*u1.x + a2*u2.x;
        m.y = a0*u0.y + a1*u1.y + a2*u2.y;
        m.z = a0*u0.z + a1*u1.z + a2*u2.z;
        m.w = a0*u0.w + a1*u1.w + a2*u2.w;
        float4 p0 = w0[i], p1 = w1[i];
        z0 += m.x*p0.x + m.y*p0.y + m.z*p0.z + m.w*p0.w;
        z1 += m.x*p1.x + m.y*p1.y + m.z*p1.z + m.w*p1.w;
    }
    g_z[2 * node]     = z0;
    g_z[2 * node + 1] = z1;
}

// ---------------- link scores ----------------
__global__ void k_score(const int* __restrict__ eli, const float* __restrict__ rel,
                        float* __restrict__ scores) {
    int idx = blockIdx.x * blockDim.x + threadIdx.x;
    if (idx >= RR * LL) return;
    int r = idx / LL;
    int l = idx - r * LL;
    int hd = eli[(size_t)r * 2 * LL + l];
    int tl = eli[(size_t)r * 2 * LL + LL + l];
    float hr = g_z[2 * hd], hi = g_z[2 * hd + 1];
    float tr = g_z[2 * tl], ti = g_z[2 * tl + 1];
    float rr = rel[2 * r], ri = rel[2 * r + 1];
    scores[idx] = hr * rr * tr + hi * rr * ti + hr * ri * ti - hi * ri * tr;
}

// ---------------- host ----------------
extern "C" void kernel_launch(void* const* d_in, const int* in_sizes, int n_in,
                              void* d_out, int out_size) {
    const float* x      = (const float*)d_in[0];
    const int*   ei     = (const int*)d_in[1];
    const int*   eli    = (const int*)d_in[2];
    const float* past1  = (const float*)d_in[3];
    const float* past2  = (const float*)d_in[4];
    const float* W1rel  = (const float*)d_in[5];
    const float* b1rel  = (const float*)d_in[6];
    const float* W1root = (const float*)d_in[7];
    const float* g1Wi   = (const float*)d_in[8];
    const float* g1Wh   = (const float*)d_in[9];
    const float* g1bi   = (const float*)d_in[10];
    const float* g1bh   = (const float*)d_in[11];
    const float* k1W    = (const float*)d_in[12];
    const float* k1b    = (const float*)d_in[13];
    const float* q1     = (const float*)d_in[14];
    const float* W2rel  = (const float*)d_in[15];
    const float* b2rel  = (const float*)d_in[16];
    const float* W2root = (const float*)d_in[17];
    const float* g2Wi   = (const float*)d_in[18];
    const float* g2Wh   = (const float*)d_in[19];
    const float* g2bi   = (const float*)d_in[20];
    const float* g2bh   = (const float*)d_in[21];
    const float* k2W    = (const float*)d_in[22];
    const float* k2b    = (const float*)d_in[23];
    const float* q2     = (const float*)d_in[24];
    const float* postW  = (const float*)d_in[25];
    const float* postb  = (const float*)d_in[26];
    const float* relemb = (const float*)d_in[27];

    float* out    = (float*)d_out;
    float* scores = out;
    float* cur1   = out + (size_t)RR * LL;
    float* cur2   = cur1 + (size_t)RR * NN * 64;

    dim3 gridL((NN + 127) / 128, RR);   // 782 x 3
    const int scat_blocks = (RR * EE * 16 + 255) / 256;

    // 1: zero both agg halves + scores
    k_zeroall<<<(2 * RR * NN * 16 + 255) / 256, 256>>>();
    // 2: presplit all weights (both layers)
    k_presplit<<<(2 * WF_LAYER + 255) / 256, 256>>>(
        W1rel, W1root, g1Wi, g1Wh, k1W, W2rel, W2root, g2Wi, g2Wh, k2W);
    // 3: layer-1 scatter
    k_scatter<<<scat_blocks, 256>>>(x, 0, ei);
    // 4: fused layer 1 (conv+gru+att)
    k_layer<<<gridL, 256>>>(x, 0, past1, b1rel, g1bi, g1bh, k1b, q1, cur1);
    // 5: softmax+mix
    k_mix<<<(NN * 16 + 255) / 256, 256>>>(cur1);
    // 6: layer-2 scatter  (profiled launch under -s 5 -c 1)
    k_scatter<<<scat_blocks, 256>>>(x, 1, ei);
    // 7: fused layer 2
    k_layer<<<gridL, 256>>>(x, 1, past2, b2rel, g2bi, g2bh, k2b, q2, cur2);
    // 8: softmax+projection
    k_zfuse<<<(NN + 127) / 128, 128>>>(cur2, postW, postb);
    // 9: link scores
    k_score<<<(RR * LL + 255) / 256, 256>>>(eli, relemb, scores);
}